// round 8
// baseline (speedup 1.0000x reference)
#include <cuda_runtime.h>
#include <math.h>

// NTM shapes
#define Bb 256
#define Tt 128
#define Ii 512
#define Hh 512
#define Nn 1024
#define Mm 512
#define Oo 512
#define NBLK 148
#define NTHR 512
#define BH (Bb * Hh)
#define BM (Bb * Mm)

typedef unsigned long long ull;

// ---------------- persistent state / scratch (device globals) ---------------
__device__ float g_mem[Nn * Mm];
__device__ float g_wr[Bb * Nn];
__device__ float g_ww[Bb * Nn];
__device__ float g_h[Bb * Hh];
__device__ float g_ea[Bb * 2 * Mm];
__device__ float g_rpart[4 * Bb * Mm];
__device__ float g_hpart[4 * Bb * Hh];
__device__ float g_pw[Bb * (Mm + 6)];
__device__ float g_pr[Bb * (Mm + 6)];
__device__ float g_scw[Bb * 8];
__device__ float g_scr[Bb * 8];
__device__ float g_simw[Bb * Nn];
__device__ float g_simr[Bb * Nn];
__device__ float g_invmem[Nn];
__device__ unsigned g_bar_count;
__device__ unsigned g_bar_gen;

// ---------------- grid barrier ----------------------------------------------
static __device__ __forceinline__ void gridBarrier() {
    __syncthreads();
    __threadfence();
    if (threadIdx.x == 0) {
        unsigned gen = *(volatile unsigned*)&g_bar_gen;
        unsigned prev = atomicAdd(&g_bar_count, 1u);
        if (prev == NBLK - 1) {
            g_bar_count = 0;
            __threadfence();
            *(volatile unsigned*)&g_bar_gen = gen + 1;
        } else {
            while (*(volatile unsigned*)&g_bar_gen == gen) { __nanosleep(64); }
        }
    }
    __syncthreads();
}

// ---------------- packed f32x2 helpers ---------------------------------------
static __device__ __forceinline__ void fmax2(ull &d, ull a, ull b) {
    asm("fma.rn.f32x2 %0, %1, %2, %3;" : "=l"(d) : "l"(a), "l"(b), "l"(d));
}
static __device__ __forceinline__ float2 unpack2(ull v) {
    float2 f;
    asm("mov.b64 {%0, %1}, %2;" : "=f"(f.x), "=f"(f.y) : "l"(v));
    return f;
}
static __device__ __forceinline__ float psum(ull v) {
    float2 f = unpack2(v);
    return f.x + f.y;
}

// ---------------- math helpers ----------------------------------------------
static __device__ __forceinline__ float sigm(float x) { return 1.f / (1.f + __expf(-x)); }
static __device__ __forceinline__ float tanh_f(float x) {
    float t = __expf(-2.f * fabsf(x));
    float r = (1.f - t) / (1.f + t);
    return copysignf(r, x);
}
static __device__ __forceinline__ float softplus_(float x) {
    return fmaxf(x, 0.f) + log1pf(__expf(-fabsf(x)));
}
static __device__ __forceinline__ float warpReduceSum(float v) {
    #pragma unroll
    for (int o = 16; o > 0; o >>= 1) v += __shfl_xor_sync(0xffffffffu, v, o);
    return v;
}
static __device__ __forceinline__ float warpReduceMax(float v) {
    #pragma unroll
    for (int o = 16; o > 0; o >>= 1) v = fmaxf(v, __shfl_xor_sync(0xffffffffu, v, o));
    return v;
}
static __device__ __forceinline__ float blockReduceSum512(float v) {
    __shared__ float sh[16];
    int lane = threadIdx.x & 31, wid = threadIdx.x >> 5;
    v = warpReduceSum(v);
    if (lane == 0) sh[wid] = v;
    __syncthreads();
    if (wid == 0) {
        float t = (lane < 16) ? sh[lane] : 0.f;
        t = warpReduceSum(t);
        if (lane == 0) sh[0] = t;
    }
    __syncthreads();
    float r = sh[0];
    __syncthreads();
    return r;
}
static __device__ __forceinline__ float blockReduceMax512(float v) {
    __shared__ float sh[16];
    int lane = threadIdx.x & 31, wid = threadIdx.x >> 5;
    v = warpReduceMax(v);
    if (lane == 0) sh[wid] = v;
    __syncthreads();
    if (wid == 0) {
        float t = (lane < 16) ? sh[lane] : -3.4e38f;
        t = warpReduceMax(t);
        if (lane == 0) sh[0] = t;
    }
    __syncthreads();
    float r = sh[0];
    __syncthreads();
    return r;
}

// k-interleaved operand staging: per operand 2 bufs x 8 kkpairs x 68 ull
// buf stride = 544 ull = 1088 floats
#define OPB 544

// inner step: 2 row-pairs x 4 cols
#define FMA2x4(acc, a2, w0, w1, w2, w3)                               \
    {                                                                  \
        fmax2(acc[0][0], a2.x, w0); fmax2(acc[0][1], a2.x, w1);        \
        fmax2(acc[0][2], a2.x, w2); fmax2(acc[0][3], a2.x, w3);        \
        fmax2(acc[1][0], a2.y, w0); fmax2(acc[1][1], a2.y, w1);        \
        fmax2(acc[1][2], a2.y, w2); fmax2(acc[1][3], a2.y, w3);        \
    }

// ---------------- 64x64 NN GEMM tile: C = act(A@W + bias) --------------------
// act: 0 none, 2 sigmoid, 3 tanh col<512, 4 sigmoid col<512 | tanh col>=512.
// compute map: rows ty*2+{0,1} (ty=tid>>4), cols tx+{0,16,32,48} (tx=tid&15)
static __device__ __forceinline__ void gemm64_nn(
    const float* __restrict__ A, int lda,
    const float* __restrict__ W, int ldw,
    const float* __restrict__ bias,
    float* __restrict__ C, int ldc,
    int bm, int bn, int Nc, int K, int act, float* shb)
{
    ull* Au = (ull*)shb;
    ull* Wu = (ull*)shb + 2 * OPB;
    float* Af = (float*)Au;
    float* Wf = (float*)Wu;
    const int tid = threadIdx.x;
    const int tx = tid & 15, ty = tid >> 4;
    const int am = tid >> 4, ak = tid & 15;      // A loader: rows am, am+32
    const int wk = tid >> 6, wn = tid & 63;      // W loader: ks wk, wk+8
    const float* Ap = A + (size_t)(bm + am) * lda + ak;
    const float* Wp = W + (size_t)wk * ldw + bn + wn;
    const bool wok = (bn + wn) < Nc;
    const int ai0 = ((ak >> 1) * 68 + am) * 2 + (ak & 1);
    const int ai1 = ((ak >> 1) * 68 + am + 32) * 2 + (ak & 1);
    const int wi0 = ((wk >> 1) * 68 + wn) * 2 + (wk & 1);
    const int wi1 = ((4 + (wk >> 1)) * 68 + wn) * 2 + (wk & 1);

    ull acc[2][4] = {};
    float ra0 = Ap[0], ra1 = Ap[(size_t)32 * lda];
    float rw0 = wok ? Wp[0] : 0.f, rw1 = wok ? Wp[(size_t)8 * ldw] : 0.f;
    Af[ai0] = ra0; Af[ai1] = ra1;
    Wf[wi0] = rw0; Wf[wi1] = rw1;
    __syncthreads();
    int buf = 0;
    for (int k0 = 0; k0 < K; k0 += 16) {
        if (k0 + 16 < K) {
            ra0 = Ap[k0 + 16]; ra1 = Ap[(size_t)32 * lda + k0 + 16];
            const float* Wp2 = Wp + (size_t)(k0 + 16) * ldw;
            rw0 = wok ? Wp2[0] : 0.f; rw1 = wok ? Wp2[(size_t)8 * ldw] : 0.f;
        }
        const ull* Ab = Au + buf * OPB;
        const ull* Wb = Wu + buf * OPB;
        #pragma unroll
        for (int kp = 0; kp < 8; kp++) {
            ulonglong2 a2 = *(const ulonglong2*)(Ab + kp * 68 + ty * 2);
            ull w0 = Wb[kp * 68 + tx];
            ull w1 = Wb[kp * 68 + tx + 16];
            ull w2 = Wb[kp * 68 + tx + 32];
            ull w3 = Wb[kp * 68 + tx + 48];
            FMA2x4(acc, a2, w0, w1, w2, w3);
        }
        if (k0 + 16 < K) {
            __syncthreads();
            int nb = buf ^ 1;
            Af[nb * 1088 + ai0] = ra0; Af[nb * 1088 + ai1] = ra1;
            Wf[nb * 1088 + wi0] = rw0; Wf[nb * 1088 + wi1] = rw1;
            __syncthreads();
            buf = nb;
        }
    }
    __syncthreads();
    #pragma unroll
    for (int r = 0; r < 2; r++) {
        int row = bm + ty * 2 + r;
        #pragma unroll
        for (int j = 0; j < 4; j++) {
            int col = bn + tx + j * 16;
            if (col >= Nc) continue;
            float v = psum(acc[r][j]);
            if (bias) v += bias[col];
            if (act == 2) v = sigm(v);
            else if (act == 3) { if (col < 512) v = tanh_f(v); }
            else if (act == 4) { v = (col < 512) ? sigm(v) : tanh_f(v); }
            C[(size_t)row * ldc + col] = v;
        }
    }
}

// ---------------- 64x64 NT GEMM tile: C[b,n] = sum_k A[b,k]*Bm[n,k] ---------
static __device__ __forceinline__ void gemm64_nt(
    const float* __restrict__ A, int lda,
    const float* __restrict__ Bm, int ldb,
    float* __restrict__ C, int ldc,
    int bm, int bn, int K, float* shb)
{
    ull* Au = (ull*)shb;
    ull* Wu = (ull*)shb + 2 * OPB;
    float* Af = (float*)Au;
    float* Wf = (float*)Wu;
    const int tid = threadIdx.x;
    const int tx = tid & 15, ty = tid >> 4;
    const int am = tid >> 4, ak = tid & 15;
    const float* Ap = A + (size_t)(bm + am) * lda + ak;
    const float* Bp = Bm + (size_t)(bn + am) * ldb + ak;    // A-style loader (coalesced)
    const int ai0 = ((ak >> 1) * 68 + am) * 2 + (ak & 1);
    const int ai1 = ((ak >> 1) * 68 + am + 32) * 2 + (ak & 1);

    ull acc[2][4] = {};
    float ra0 = Ap[0], ra1 = Ap[(size_t)32 * lda];
    float rb0 = Bp[0], rb1 = Bp[(size_t)32 * ldb];
    Af[ai0] = ra0; Af[ai1] = ra1;
    Wf[ai0] = rb0; Wf[ai1] = rb1;
    __syncthreads();
    int buf = 0;
    for (int k0 = 0; k0 < K; k0 += 16) {
        if (k0 + 16 < K) {
            ra0 = Ap[k0 + 16]; ra1 = Ap[(size_t)32 * lda + k0 + 16];
            rb0 = Bp[k0 + 16]; rb1 = Bp[(size_t)32 * ldb + k0 + 16];
        }
        const ull* Ab = Au + buf * OPB;
        const ull* Wb = Wu + buf * OPB;
        #pragma unroll
        for (int kp = 0; kp < 8; kp++) {
            ulonglong2 a2 = *(const ulonglong2*)(Ab + kp * 68 + ty * 2);
            ull w0 = Wb[kp * 68 + tx];
            ull w1 = Wb[kp * 68 + tx + 16];
            ull w2 = Wb[kp * 68 + tx + 32];
            ull w3 = Wb[kp * 68 + tx + 48];
            FMA2x4(acc, a2, w0, w1, w2, w3);
        }
        if (k0 + 16 < K) {
            __syncthreads();
            int nb = buf ^ 1;
            Af[nb * 1088 + ai0] = ra0; Af[nb * 1088 + ai1] = ra1;
            Wf[nb * 1088 + ai0] = rb0; Wf[nb * 1088 + ai1] = rb1;
            __syncthreads();
            buf = nb;
        }
    }
    __syncthreads();
    #pragma unroll
    for (int r = 0; r < 2; r++) {
        int row = bm + ty * 2 + r;
        #pragma unroll
        for (int j = 0; j < 4; j++)
            C[(size_t)row * ldc + (bn + tx + j * 16)] = psum(acc[r][j]);
    }
}

// ---------------- mem update tile: mem = mem*(1 - ww^T e/B) + ww^T a/B ------
static __device__ __forceinline__ void memupd_tile(int tn, int tm, float* shb)
{
    ull* Nu = (ull*)shb;                  // ww (n-side, output rows)
    ull* Eu = (ull*)shb + 2 * OPB;
    ull* Aau = (ull*)shb + 4 * OPB;
    float* Nf = (float*)Nu;
    float* Ef = (float*)Eu;
    float* Aaf = (float*)Aau;
    const int bnrow = tn * 64, bmcol = tm * 64;
    const int tid = threadIdx.x;
    const int tx = tid & 15, ty = tid >> 4;
    const int wk = tid >> 6, wn = tid & 63;      // W-style loader for all 3 operands
    const float* wp = g_ww + (size_t)wk * Nn + bnrow + wn;
    const float* ep = g_ea + (size_t)wk * (2 * Mm) + bmcol + wn;
    const float* ap = ep + Mm;
    const int wi0 = ((wk >> 1) * 68 + wn) * 2 + (wk & 1);
    const int wi1 = ((4 + (wk >> 1)) * 68 + wn) * 2 + (wk & 1);

    ull acce[2][4] = {};
    ull acca[2][4] = {};
    float rw0 = wp[0], rw1 = wp[(size_t)8 * Nn];
    float re0 = ep[0], re1 = ep[(size_t)8 * (2 * Mm)];
    float rr0 = ap[0], rr1 = ap[(size_t)8 * (2 * Mm)];
    Nf[wi0] = rw0; Nf[wi1] = rw1;
    Ef[wi0] = re0; Ef[wi1] = re1;
    Aaf[wi0] = rr0; Aaf[wi1] = rr1;
    __syncthreads();
    int buf = 0;
    for (int b0 = 0; b0 < Bb; b0 += 16) {
        if (b0 + 16 < Bb) {
            const float* wp2 = wp + (size_t)(b0 + 16) * Nn;
            const float* ep2 = ep + (size_t)(b0 + 16) * (2 * Mm);
            const float* ap2 = ap + (size_t)(b0 + 16) * (2 * Mm);
            rw0 = wp2[0]; rw1 = wp2[(size_t)8 * Nn];
            re0 = ep2[0]; re1 = ep2[(size_t)8 * (2 * Mm)];
            rr0 = ap2[0]; rr1 = ap2[(size_t)8 * (2 * Mm)];
        }
        const ull* Nb = Nu + buf * OPB;
        const ull* Eb = Eu + buf * OPB;
        const ull* Ab = Aau + buf * OPB;
        #pragma unroll
        for (int kp = 0; kp < 8; kp++) {
            ulonglong2 n2 = *(const ulonglong2*)(Nb + kp * 68 + ty * 2);
            ull e0 = Eb[kp * 68 + tx],      e1 = Eb[kp * 68 + tx + 16];
            ull e2 = Eb[kp * 68 + tx + 32], e3 = Eb[kp * 68 + tx + 48];
            ull a0 = Ab[kp * 68 + tx],      a1 = Ab[kp * 68 + tx + 16];
            ull a2 = Ab[kp * 68 + tx + 32], a3 = Ab[kp * 68 + tx + 48];
            FMA2x4(acce, n2, e0, e1, e2, e3);
            FMA2x4(acca, n2, a0, a1, a2, a3);
        }
        if (b0 + 16 < Bb) {
            __syncthreads();
            int nb = buf ^ 1;
            Nf[nb * 1088 + wi0] = rw0; Nf[nb * 1088 + wi1] = rw1;
            Ef[nb * 1088 + wi0] = re0; Ef[nb * 1088 + wi1] = re1;
            Aaf[nb * 1088 + wi0] = rr0; Aaf[nb * 1088 + wi1] = rr1;
            __syncthreads();
            buf = nb;
        }
    }
    __syncthreads();
    const float invB = 1.f / (float)Bb;
    #pragma unroll
    for (int r = 0; r < 2; r++) {
        int n = bnrow + ty * 2 + r;
        #pragma unroll
        for (int j = 0; j < 4; j++) {
            int m = bmcol + tx + j * 16;
            float ev = psum(acce[r][j]);
            float av = psum(acca[r][j]);
            float old = g_mem[(size_t)n * Mm + m];
            g_mem[(size_t)n * Mm + m] = old * (1.f - ev * invB) + av * invB;
        }
    }
}

// ---------------- controller split-K tile ------------------------------------
// chunk c: 0,1 -> x halves; 2,3 -> r (= sum of 4 rpart) halves. K=256 each.
static __device__ __forceinline__ void gemmD_tile(
    int c, int bm, int bn, const float* __restrict__ xb,
    const float* __restrict__ Wx, const float* __restrict__ Wr, float* shb)
{
    ull* Au = (ull*)shb;
    ull* Wu = (ull*)shb + 2 * OPB;
    float* Af = (float*)Au;
    float* Wf = (float*)Wu;
    const int tid = threadIdx.x;
    const int tx = tid & 15, ty = tid >> 4;
    const int am = tid >> 4, ak = tid & 15;
    const int wk = tid >> 6, wn = tid & 63;
    const float* Wp = ((c < 2) ? (Wx + (size_t)c * 256 * Hh)
                               : (Wr + (size_t)(c - 2) * 256 * Hh))
                      + (size_t)wk * Hh + bn + wn;
    const float* Ax = xb + (size_t)(bm + am) * (Tt * Ii) + c * 256 + ak;
    const float* Ar = g_rpart + (size_t)(bm + am) * Mm + (c - 2) * 256 + ak;
    const int ai0 = ((ak >> 1) * 68 + am) * 2 + (ak & 1);
    const int ai1 = ((ak >> 1) * 68 + am + 32) * 2 + (ak & 1);
    const int wi0 = ((wk >> 1) * 68 + wn) * 2 + (wk & 1);
    const int wi1 = ((4 + (wk >> 1)) * 68 + wn) * 2 + (wk & 1);

    ull acc[2][4] = {};
    float ra0, ra1;
    if (c < 2) {
        ra0 = Ax[0]; ra1 = Ax[(size_t)32 * (Tt * Ii)];
    } else {
        const float* p0 = Ar;
        const float* p1 = Ar + (size_t)32 * Mm;
        ra0 = p0[0] + p0[BM] + p0[2 * BM] + p0[3 * BM];
        ra1 = p1[0] + p1[BM] + p1[2 * BM] + p1[3 * BM];
    }
    float rw0 = Wp[0], rw1 = Wp[(size_t)8 * Hh];
    Af[ai0] = ra0; Af[ai1] = ra1;
    Wf[wi0] = rw0; Wf[wi1] = rw1;
    __syncthreads();
    int buf = 0;
    for (int k0 = 0; k0 < 256; k0 += 16) {
        if (k0 + 16 < 256) {
            if (c < 2) {
                ra0 = Ax[k0 + 16];
                ra1 = Ax[(size_t)32 * (Tt * Ii) + k0 + 16];
            } else {
                const float* p0 = Ar + k0 + 16;
                const float* p1 = Ar + (size_t)32 * Mm + k0 + 16;
                ra0 = p0[0] + p0[BM] + p0[2 * BM] + p0[3 * BM];
                ra1 = p1[0] + p1[BM] + p1[2 * BM] + p1[3 * BM];
            }
            const float* Wp2 = Wp + (size_t)(k0 + 16) * Hh;
            rw0 = Wp2[0]; rw1 = Wp2[(size_t)8 * Hh];
        }
        const ull* Ab = Au + buf * OPB;
        const ull* Wb = Wu + buf * OPB;
        #pragma unroll
        for (int kp = 0; kp < 8; kp++) {
            ulonglong2 a2 = *(const ulonglong2*)(Ab + kp * 68 + ty * 2);
            ull w0 = Wb[kp * 68 + tx];
            ull w1 = Wb[kp * 68 + tx + 16];
            ull w2 = Wb[kp * 68 + tx + 32];
            ull w3 = Wb[kp * 68 + tx + 48];
            FMA2x4(acc, a2, w0, w1, w2, w3);
        }
        if (k0 + 16 < 256) {
            __syncthreads();
            int nb = buf ^ 1;
            Af[nb * 1088 + ai0] = ra0; Af[nb * 1088 + ai1] = ra1;
            Wf[nb * 1088 + wi0] = rw0; Wf[nb * 1088 + wi1] = rw1;
            __syncthreads();
            buf = nb;
        }
    }
    __syncthreads();
    float* C = g_hpart + (size_t)c * BH;
    #pragma unroll
    for (int r = 0; r < 2; r++) {
        int row = bm + ty * 2 + r;
        #pragma unroll
        for (int j = 0; j < 4; j++)
            C[(size_t)row * Hh + (bn + tx + j * 16)] = psum(acc[r][j]);
    }
}

// ---------------- small row-wise items ---------------------------------------
static __device__ __noinline__ void invnorm_item(int item)
{
    int w = threadIdx.x >> 5, lane = threadIdx.x & 31;
    for (int rr = w; rr < 128; rr += 16) {
        int n = item * 128 + rr;
        float s = 0.f;
        for (int c = lane; c < Mm; c += 32) {
            float v = g_mem[(size_t)n * Mm + c];
            s += v * v;
        }
        s = warpReduceSum(s);
        if (lane == 0) g_invmem[n] = 1.f / (sqrtf(s) + 1e-8f);
    }
}

static __device__ __noinline__ void scalars_item(int i)
{
    int head = i >> 3, rb = i & 7;
    const float* p = head ? g_pr : g_pw;
    float* sc = head ? g_scr : g_scw;
    int w = threadIdx.x >> 5, lane = threadIdx.x & 31;
    for (int rr = w; rr < 32; rr += 16) {
        int b = rb * 32 + rr;
        const float* row = p + (size_t)b * (Mm + 6);
        float s = 0.f;
        for (int c = lane; c < Mm; c += 32) {
            float v = row[c];
            s += v * v;
        }
        s = warpReduceSum(s);
        if (lane == 0) {
            sc[b * 8 + 0] = softplus_(row[Mm + 0]);
            sc[b * 8 + 1] = sigm(row[Mm + 1]);
            float s0 = row[Mm + 2], s1 = row[Mm + 3], s2 = row[Mm + 4];
            float mx = fmaxf(s0, fmaxf(s1, s2));
            float e0 = __expf(s0 - mx), e1 = __expf(s1 - mx), e2 = __expf(s2 - mx);
            float inv = 1.f / (e0 + e1 + e2);
            sc[b * 8 + 2] = e0 * inv;
            sc[b * 8 + 3] = e1 * inv;
            sc[b * 8 + 4] = e2 * inv;
            sc[b * 8 + 5] = 1.f + softplus_(row[Mm + 5]);
            sc[b * 8 + 6] = 1.f / (sqrtf(s) + 1e-8f);
        }
    }
}

// -------- fused address tail: softmax -> interpolate -> shift -> sharpen -----
static __device__ __noinline__ void tail_item(int it, float* shb)
{
    float* wg = shb;                  // 1024 floats
    int b = it & 255, head = it >> 8;
    const float* sim = head ? g_simr : g_simw;
    float* wv = head ? g_wr : g_ww;
    const float* sc = head ? g_scr : g_scw;
    int tid = threadIdx.x;
    float beta = sc[b * 8 + 0], g = sc[b * 8 + 1];
    float s0 = sc[b * 8 + 2], s1 = sc[b * 8 + 3], s2 = sc[b * 8 + 4];
    float gamma = sc[b * 8 + 5], invk = sc[b * 8 + 6];
    float scale = beta * invk;

    float v[2];
    float mx = -3.4e38f;
    #pragma unroll
    for (int i = 0; i < 2; i++) {
        int n = tid + i * 512;
        float t = sim[(size_t)b * Nn + n] * scale * g_invmem[n];
        v[i] = t;
        mx = fmaxf(mx, t);
    }
    mx = blockReduceMax512(mx);
    float s = 0.f;
    #pragma unroll
    for (int i = 0; i < 2; i++) { v[i] = __expf(v[i] - mx); s += v[i]; }
    s = blockReduceSum512(s);
    float invs = 1.f / s;
    #pragma unroll
    for (int i = 0; i < 2; i++) {
        int n = tid + i * 512;
        wg[n] = g * (v[i] * invs) + (1.f - g) * wv[(size_t)b * Nn + n];
    }
    __syncthreads();
    float wp[2];
    float local = 0.f;
    #pragma unroll
    for (int i = 0; i < 2; i++) {
        int n = tid + i * 512;
        float wt = s0 * wg[(n + 1) & (Nn - 1)] + s1 * wg[n] + s2 * wg[(n - 1) & (Nn - 1)];
        float pv = __powf(wt, gamma);
        wp[i] = pv;
        local += pv;
    }
    local = blockReduceSum512(local);
    float invt = 1.f / (local + 1e-8f);
    #pragma unroll
    for (int i = 0; i < 2; i++) {
        int n = tid + i * 512;
        wv[(size_t)b * Nn + n] = wp[i] * invt;
    }
    __syncthreads();
}

// ---------------- the persistent kernel --------------------------------------
__global__ void __launch_bounds__(NTHR, 1) ntm_persistent(
    const float* __restrict__ x,
    const float* __restrict__ mem0, const float* __restrict__ wr0,
    const float* __restrict__ ww0,  const float* __restrict__ h0,
    const float* __restrict__ Wx,   const float* __restrict__ Wr,
    const float* __restrict__ bh,
    const float* __restrict__ Whr,  const float* __restrict__ bhr,
    const float* __restrict__ Whw,  const float* __restrict__ bhw,
    const float* __restrict__ Wea,  const float* __restrict__ bea,
    const float* __restrict__ Wo,   const float* __restrict__ bo,
    float* __restrict__ out)
{
    // 3 operands x 2 bufs x 544 ull = 26112 bytes
    __shared__ __align__(16) float shbuf[6528];
    const int tid = threadIdx.x;
    const int gtid = blockIdx.x * NTHR + tid;
    const int gstride = NBLK * NTHR;

    // P0: init carried state
    for (int i = gtid; i < Nn * Mm; i += gstride) g_mem[i] = mem0[i];
    for (int i = gtid; i < Bb * Nn; i += gstride) { g_wr[i] = wr0[i]; g_ww[i] = ww0[i]; }
    for (int i = gtid; i < Bb * Hh; i += gstride) g_h[i] = h0[i];
    gridBarrier();

    // P1: ea from h0 (64 tiles)
    for (int it = blockIdx.x; it < 64; it += NBLK) {
        int tm = it >> 4, tn = it & 15;
        gemm64_nn(g_h, Hh, Wea, 2 * Mm, bea, g_ea, 2 * Mm,
                  tm * 64, tn * 64, 2 * Mm, Hh, 4, shbuf);
    }
    gridBarrier();

    for (int t = 0; t < Tt; t++) {
        // B: memupd (128) + out_{t-1} tiles 0..19  => exactly 148 items
        for (int it = blockIdx.x; it < 148; it += NBLK) {
            if (it < 128) memupd_tile(it >> 3, it & 7, shbuf);
            else if (t > 0) {
                int o = it - 128;                         // 0..19
                gemm64_nn(g_h, Hh, Wo, Oo, bo, out + (size_t)(t - 1) * Oo, Tt * Oo,
                          (o >> 3) * 64, (o & 7) * 64, Oo, Hh, 2, shbuf);
            }
        }
        gridBarrier();

        // C: r split-K (128) + invnorm (8) + out_{t-1} tiles 20..31 => 148
        for (int it = blockIdx.x; it < 148; it += NBLK) {
            if (it < 128) {
                int c = it >> 5, rest = it & 31, tm = rest >> 3, tn = rest & 7;
                gemm64_nn(g_wr + c * 256, Nn, g_mem + (size_t)c * 256 * Mm, Mm, nullptr,
                          g_rpart + (size_t)c * BM, Mm, tm * 64, tn * 64, Mm, 256, 0, shbuf);
            } else if (it < 136) invnorm_item(it - 128);
            else if (t > 0) {
                int o = it - 136 + 20;                    // 20..31
                gemm64_nn(g_h, Hh, Wo, Oo, bo, out + (size_t)(t - 1) * Oo, Tt * Oo,
                          (o >> 3) * 64, (o & 7) * 64, Oo, Hh, 2, shbuf);
            }
        }
        gridBarrier();

        // D: controller split-K (128)
        for (int it = blockIdx.x; it < 128; it += NBLK) {
            int c = it >> 5, rest = it & 31, tm = rest >> 3, tn = rest & 7;
            gemmD_tile(c, tm * 64, tn * 64, x + (size_t)t * Ii, Wx, Wr, shbuf);
        }
        gridBarrier();

        // D2: h = tanh(sum hpart + bh)
        for (int i = gtid; i < BH; i += gstride)
            g_h[i] = tanh_f(g_hpart[i] + g_hpart[i + BH] + g_hpart[i + 2 * BH]
                            + g_hpart[i + 3 * BH] + bh[i & 511]);
        gridBarrier();

        // E: pw(36) + pr(36) + ea-next(64) = 136 items, single round
        for (int it = blockIdx.x; it < 136; it += NBLK) {
            if (it < 36) {
                int tm = it / 9, tn = it % 9;
                gemm64_nn(g_h, Hh, Whw, Mm + 6, bhw, g_pw, Mm + 6,
                          tm * 64, tn * 64, Mm + 6, Hh, 3, shbuf);
            } else if (it < 72) {
                int i2 = it - 36, tm = i2 / 9, tn = i2 % 9;
                gemm64_nn(g_h, Hh, Whr, Mm + 6, bhr, g_pr, Mm + 6,
                          tm * 64, tn * 64, Mm + 6, Hh, 3, shbuf);
            } else {
                int i2 = it - 72, tm = i2 >> 4, tn = i2 & 15;
                gemm64_nn(g_h, Hh, Wea, 2 * Mm, bea, g_ea, 2 * Mm,
                          tm * 64, tn * 64, 2 * Mm, Hh, 4, shbuf);
            }
        }
        gridBarrier();

        // F: simw(64) simr(64) + head scalars(16) = 144
        for (int it = blockIdx.x; it < 144; it += NBLK) {
            if (it < 64) {
                int tm = it >> 4, tn = it & 15;
                gemm64_nt(g_pw, Mm + 6, g_mem, Mm, g_simw, Nn,
                          tm * 64, tn * 64, Mm, shbuf);
            } else if (it < 128) {
                int i2 = it - 64, tm = i2 >> 4, tn = i2 & 15;
                gemm64_nt(g_pr, Mm + 6, g_mem, Mm, g_simr, Nn,
                          tm * 64, tn * 64, Mm, shbuf);
            } else scalars_item(it - 128);
        }
        gridBarrier();

        // G: address tails (512 rows)
        for (int it = blockIdx.x; it < 512; it += NBLK)
            tail_item(it, shbuf);
        gridBarrier();
    }

    // final out for t = 127 (h still holds h_127)
    for (int it = blockIdx.x; it < 32; it += NBLK) {
        gemm64_nn(g_h, Hh, Wo, Oo, bo, out + (size_t)(Tt - 1) * Oo, Tt * Oo,
                  (it >> 3) * 64, (it & 7) * 64, Oo, Hh, 2, shbuf);
    }
}

// ---------------- host --------------------------------------------------------
extern "C" void kernel_launch(void* const* d_in, const int* in_sizes, int n_in,
                              void* d_out, int out_size)
{
    const float* x    = (const float*)d_in[0];
    const float* mem0 = (const float*)d_in[1];
    const float* wr0  = (const float*)d_in[2];
    const float* ww0  = (const float*)d_in[3];
    const float* h0   = (const float*)d_in[4];
    const float* Wx   = (const float*)d_in[5];
    const float* Wr   = (const float*)d_in[6];
    const float* bh   = (const float*)d_in[7];
    const float* Whr  = (const float*)d_in[8];
    const float* bhr  = (const float*)d_in[9];
    const float* Whw  = (const float*)d_in[10];
    const float* bhw  = (const float*)d_in[11];
    const float* Wea  = (const float*)d_in[12];
    const float* bea  = (const float*)d_in[13];
    const float* Wo   = (const float*)d_in[14];
    const float* bo   = (const float*)d_in[15];
    float* out = (float*)d_out;

    ntm_persistent<<<NBLK, NTHR>>>(x, mem0, wr0, ww0, h0, Wx, Wr, bh,
                                   Whr, bhr, Whw, bhw, Wea, bea, Wo, bo, out);
}

// round 9
// speedup vs baseline: 1.2396x; 1.2396x over previous
#include <cuda_runtime.h>
#include <math.h>

#define Bb 256
#define Tt 128
#define Ii 512
#define Hh 512
#define Nn 1024
#define Mm 512
#define Oo 512
#define NBLK 148
#define NTHR 256
#define BH (Bb * Hh)
#define BM (Bb * Mm)

typedef unsigned int u32;

__device__ float g_mem[Nn * Mm];
__device__ float g_wr[Bb * Nn];
__device__ float g_ww[Bb * Nn];
__device__ float g_h[Bb * Hh];
__device__ float g_ea[Bb * 2 * Mm];
__device__ float g_rpart[4 * Bb * Mm];
__device__ float g_hpart[4 * Bb * Hh];
__device__ float g_pw[Bb * (Mm + 6)];
__device__ float g_pr[Bb * (Mm + 6)];
__device__ float g_scw[Bb * 8];
__device__ float g_scr[Bb * 8];
__device__ float g_simw[Bb * Nn];
__device__ float g_simr[Bb * Nn];
__device__ float g_invmem[Nn];
__device__ unsigned g_bar_count;
__device__ unsigned g_bar_gen;

static __device__ __forceinline__ void gridBarrier() {
    __syncthreads();
    __threadfence();
    if (threadIdx.x == 0) {
        unsigned gen = *(volatile unsigned*)&g_bar_gen;
        unsigned prev = atomicAdd(&g_bar_count, 1u);
        if (prev == NBLK - 1) {
            g_bar_count = 0;
            __threadfence();
            *(volatile unsigned*)&g_bar_gen = gen + 1;
        } else {
            while (*(volatile unsigned*)&g_bar_gen == gen) { __nanosleep(64); }
        }
    }
    __syncthreads();
}

// ---------------- math helpers ----------------------------------------------
static __device__ __forceinline__ float sigm(float x) { return 1.f / (1.f + __expf(-x)); }
static __device__ __forceinline__ float tanh_f(float x) {
    float t = __expf(-2.f * fabsf(x));
    float r = (1.f - t) / (1.f + t);
    return copysignf(r, x);
}
static __device__ __forceinline__ float softplus_(float x) {
    return fmaxf(x, 0.f) + log1pf(__expf(-fabsf(x)));
}
static __device__ __forceinline__ float warpReduceSum(float v) {
    #pragma unroll
    for (int o = 16; o > 0; o >>= 1) v += __shfl_xor_sync(0xffffffffu, v, o);
    return v;
}
static __device__ __forceinline__ float warpReduceMax(float v) {
    #pragma unroll
    for (int o = 16; o > 0; o >>= 1) v = fmaxf(v, __shfl_xor_sync(0xffffffffu, v, o));
    return v;
}
static __device__ __forceinline__ float blockReduceSum256(float v) {
    __shared__ float sh[8];
    int lane = threadIdx.x & 31, wid = threadIdx.x >> 5;
    v = warpReduceSum(v);
    if (lane == 0) sh[wid] = v;
    __syncthreads();
    if (wid == 0) {
        float t = (lane < 8) ? sh[lane] : 0.f;
        t = warpReduceSum(t);
        if (lane == 0) sh[0] = t;
    }
    __syncthreads();
    float r = sh[0];
    __syncthreads();
    return r;
}
static __device__ __forceinline__ float blockReduceMax256(float v) {
    __shared__ float sh[8];
    int lane = threadIdx.x & 31, wid = threadIdx.x >> 5;
    v = warpReduceMax(v);
    if (lane == 0) sh[wid] = v;
    __syncthreads();
    if (wid == 0) {
        float t = (lane < 8) ? sh[lane] : -3.4e38f;
        t = warpReduceMax(t);
        if (lane == 0) sh[0] = t;
    }
    __syncthreads();
    float r = sh[0];
    __syncthreads();
    return r;
}

// ---------------- bf16 split + mma -------------------------------------------
// pack (x0,x1): low half = bf16(x0) (even k), high = bf16(x1)
static __device__ __forceinline__ void split2(float x0, float x1, u32 &hi, u32 &lo) {
    u32 h;
    asm("cvt.rn.bf16x2.f32 %0, %1, %2;" : "=r"(h) : "f"(x1), "f"(x0));
    float h0 = __uint_as_float(h << 16);
    float h1 = __uint_as_float(h & 0xffff0000u);
    asm("cvt.rn.bf16x2.f32 %0, %1, %2;" : "=r"(lo) : "f"(x1 - h1), "f"(x0 - h0));
    hi = h;
}
static __device__ __forceinline__ void mma16816(float* c,
    u32 a0, u32 a1, u32 a2, u32 a3, u32 b0, u32 b1)
{
    asm("mma.sync.aligned.m16n8k16.row.col.f32.bf16.bf16.f32 "
        "{%0,%1,%2,%3},{%4,%5,%6,%7},{%8,%9},{%0,%1,%2,%3};"
        : "+f"(c[0]), "+f"(c[1]), "+f"(c[2]), "+f"(c[3])
        : "r"(a0), "r"(a1), "r"(a2), "r"(a3), "r"(b0), "r"(b1));
}

// ---------------- staging -----------------------------------------------------
// operand plane: hi[row*20+w] (1280 u32) then lo (+1280). row = m/n idx, w = k word.
struct StR { float2 v[2]; };
static __device__ __forceinline__ StR load_rows(const float* __restrict__ A,
    size_t lda, int k0, int nsum, size_t sstr)
{
    int t = threadIdx.x;
    int row = t >> 2, w = t & 3;
    const float* p = A + (size_t)row * lda + k0 + 2 * w;
    StR s;
    #pragma unroll
    for (int i = 0; i < 2; i++) {
        float2 v = *(const float2*)(p + 8 * i);
        if (nsum == 4) {
            #pragma unroll
            for (int q = 1; q < 4; q++) {
                float2 u = *(const float2*)(p + 8 * i + q * sstr);
                v.x += u.x; v.y += u.y;
            }
        }
        s.v[i] = v;
    }
    return s;
}
static __device__ __forceinline__ void store_rows(StR s, u32* sm) {
    int t = threadIdx.x;
    int row = t >> 2, w = t & 3;
    #pragma unroll
    for (int i = 0; i < 2; i++) {
        u32 hi, lo;
        split2(s.v[i].x, s.v[i].y, hi, lo);
        sm[row * 20 + w + 4 * i] = hi;
        sm[1280 + row * 20 + w + 4 * i] = lo;
    }
}
struct StT { float v[4]; };
static __device__ __forceinline__ StT load_T(const float* __restrict__ W,
    size_t ldw, int cb, int Nc, int k0)
{
    int t = threadIdx.x;
    int p = t >> 5, n0 = t & 31;
    const float* r0 = W + (size_t)(k0 + 2 * p) * ldw + cb;
    StT s;
    #pragma unroll
    for (int i = 0; i < 2; i++) {
        int n = n0 + 32 * i;
        float v0 = 0.f, v1 = 0.f;
        if (cb + n < Nc) { v0 = r0[n]; v1 = r0[ldw + n]; }
        s.v[2 * i] = v0; s.v[2 * i + 1] = v1;
    }
    return s;
}
static __device__ __forceinline__ void store_T(StT s, u32* sm) {
    int t = threadIdx.x;
    int p = t >> 5, n0 = t & 31;
    #pragma unroll
    for (int i = 0; i < 2; i++) {
        int n = n0 + 32 * i;
        u32 hi, lo;
        split2(s.v[2 * i], s.v[2 * i + 1], hi, lo);
        sm[n * 20 + p] = hi;
        sm[1280 + n * 20 + p] = lo;
    }
}

// ---------------- warp compute for one k16 chunk ------------------------------
static __device__ __forceinline__ void mma_chunk(const u32* As, const u32* Bs,
    int wm, int wn, int lane, float acc[4][4])
{
    int r = lane >> 2, w = lane & 3;
    const u32* Ah = As + (wm * 16 + r) * 20 + w;
    u32 a0 = Ah[0], a1 = Ah[160], a2 = Ah[4], a3 = Ah[164];
    u32 e0 = Ah[1280], e1 = Ah[1440], e2 = Ah[1284], e3 = Ah[1444];
    #pragma unroll
    for (int j = 0; j < 4; j++) {
        const u32* Bh = Bs + (wn * 32 + j * 8 + r) * 20 + w;
        u32 b0 = Bh[0], b1 = Bh[4];
        u32 f0 = Bh[1280], f1 = Bh[1284];
        mma16816(acc[j], a0, a1, a2, a3, b0, b1);
        mma16816(acc[j], a0, a1, a2, a3, f0, f1);
        mma16816(acc[j], e0, e1, e2, e3, b0, b1);
    }
}

// ---------------- generic 64x64 GEMM tile -------------------------------------
// C[bm..][bn..] = act(A@W + bias); A rows at (A, lda) [+ optional 4-plane sum],
// W: trB ? stage_T from W[k][col] : direct rows W[n][k].
// act: 0 none, 2 sigmoid, 3 tanh col<512, 4 sigmoid col<512 | tanh col>=512.
static __device__ void tile_gemm(const float* __restrict__ A, size_t lda,
    int nsumA, size_t sstrA,
    const float* __restrict__ W, size_t ldw, bool trB,
    const float* __restrict__ bias,
    float* __restrict__ C, size_t ldc,
    int bn, int Nc, int K, int act, u32* shb)
{
    const int lane = threadIdx.x & 31, wid = threadIdx.x >> 5;
    const int wm = wid & 3, wn = wid >> 2;
    float acc[4][4] = {};
    u32* Ab[2] = {shb, shb + 2560};
    u32* Bf[2] = {shb + 5120, shb + 7680};

    {   // prologue chunk 0
        StR sa = load_rows(A, lda, 0, nsumA, sstrA);
        store_rows(sa, Ab[0]);
        if (trB) { StT sb = load_T(W, ldw, bn, Nc, 0); store_T(sb, Bf[0]); }
        else     { StR sb = load_rows(W + (size_t)bn * ldw, ldw, 0, 1, 0); store_rows(sb, Bf[0]); }
    }
    __syncthreads();
    for (int k0 = 0; k0 < K; k0 += 16) {
        int buf = (k0 >> 4) & 1;
        StR sa; StT sbt; StR sbr;
        bool more = (k0 + 16 < K);
        if (more) {
            sa = load_rows(A, lda, k0 + 16, nsumA, sstrA);
            if (trB) sbt = load_T(W, ldw, bn, Nc, k0 + 16);
            else     sbr = load_rows(W + (size_t)bn * ldw, ldw, k0 + 16, 1, 0);
        }
        mma_chunk(Ab[buf], Bf[buf], wm, wn, lane, acc);
        if (more) {
            store_rows(sa, Ab[buf ^ 1]);
            if (trB) store_T(sbt, Bf[buf ^ 1]);
            else     store_rows(sbr, Bf[buf ^ 1]);
        }
        __syncthreads();
    }
    // epilogue
    int r = lane >> 2, c2 = (lane & 3) * 2;
    #pragma unroll
    for (int j = 0; j < 4; j++) {
        int col0 = bn + wn * 32 + j * 8 + c2;
        #pragma unroll
        for (int rr = 0; rr < 2; rr++) {
            int row = wm * 16 + r + rr * 8;
            #pragma unroll
            for (int cc = 0; cc < 2; cc++) {
                int col = col0 + cc;
                if (col >= Nc) continue;
                float v = acc[j][rr * 2 + cc];
                if (bias) v += bias[col];
                if (act == 2) v = sigm(v);
                else if (act == 3) { if (col < 512) v = tanh_f(v); }
                else if (act == 4) { v = (col < 512) ? sigm(v) : tanh_f(v); }
                C[(size_t)row * ldc + col] = v;
            }
        }
    }
}

// ---------------- memupd tile: mem = mem*(1 - ww^T e/B) + ww^T a/B -----------
// single-buffered 3 operands: ww^T (A-side, rows=n), E, Aa (B-side, rows=m), K=Bb
static __device__ void tile_memupd(int tn, int tm, u32* shb)
{
    const int lane = threadIdx.x & 31, wid = threadIdx.x >> 5;
    const int wm = wid & 3, wn = wid >> 2;
    const int bnrow = tn * 64, bmcol = tm * 64;
    u32* Wb = shb;
    u32* Eb = shb + 2560;
    u32* Ab = shb + 5120;
    float acce[4][4] = {};
    float acca[4][4] = {};

    {
        StT sw = load_T(g_ww, Nn, bnrow, 1 << 30, 0);
        StT se = load_T(g_ea, 2 * Mm, bmcol, 1 << 30, 0);
        StT sv = load_T(g_ea, 2 * Mm, Mm + bmcol, 1 << 30, 0);
        store_T(sw, Wb); store_T(se, Eb); store_T(sv, Ab);
    }
    __syncthreads();
    for (int k0 = 0; k0 < Bb; k0 += 16) {
        StT sw, se, sv;
        bool more = (k0 + 16 < Bb);
        if (more) {
            sw = load_T(g_ww, Nn, bnrow, 1 << 30, k0 + 16);
            se = load_T(g_ea, 2 * Mm, bmcol, 1 << 30, k0 + 16);
            sv = load_T(g_ea, 2 * Mm, Mm + bmcol, 1 << 30, k0 + 16);
        }
        {   // compute: shared A-side frags, two B-sides
            int r = lane >> 2, w = lane & 3;
            const u32* Ah = Wb + (wm * 16 + r) * 20 + w;
            u32 a0 = Ah[0], a1 = Ah[160], a2 = Ah[4], a3 = Ah[164];
            u32 e0 = Ah[1280], e1 = Ah[1440], e2 = Ah[1284], e3 = Ah[1444];
            #pragma unroll
            for (int j = 0; j < 4; j++) {
                const u32* Bh = Eb + (wn * 32 + j * 8 + r) * 20 + w;
                u32 b0 = Bh[0], b1 = Bh[4], f0 = Bh[1280], f1 = Bh[1284];
                mma16816(acce[j], a0, a1, a2, a3, b0, b1);
                mma16816(acce[j], a0, a1, a2, a3, f0, f1);
                mma16816(acce[j], e0, e1, e2, e3, b0, b1);
                const u32* Ch = Ab + (wn * 32 + j * 8 + r) * 20 + w;
                u32 g0 = Ch[0], g1 = Ch[4], h0 = Ch[1280], h1 = Ch[1284];
                mma16816(acca[j], a0, a1, a2, a3, g0, g1);
                mma16816(acca[j], a0, a1, a2, a3, h0, h1);
                mma16816(acca[j], e0, e1, e2, e3, g0, g1);
            }
        }
        __syncthreads();
        if (more) {
            store_T(sw, Wb); store_T(se, Eb); store_T(sv, Ab);
        }
        __syncthreads();
    }
    const float invB = 1.f / (float)Bb;
    int r = lane >> 2, c2 = (lane & 3) * 2;
    #pragma unroll
    for (int j = 0; j < 4; j++) {
        int m0 = bmcol + wn * 32 + j * 8 + c2;
        #pragma unroll
        for (int rr = 0; rr < 2; rr++) {
            int n = bnrow + wm * 16 + r + rr * 8;
            #pragma unroll
            for (int cc = 0; cc < 2; cc++) {
                int m = m0 + cc;
                float old = g_mem[(size_t)n * Mm + m];
                g_mem[(size_t)n * Mm + m] = old * (1.f - acce[j][rr * 2 + cc] * invB)
                                            + acca[j][rr * 2 + cc] * invB;
            }
        }
    }
}

// ---------------- small row-wise items ----------------------------------------
static __device__ __noinline__ void invnorm_item(int item)
{
    int w = threadIdx.x >> 5, lane = threadIdx.x & 31;
    for (int rr = w; rr < 128; rr += 8) {
        int n = item * 128 + rr;
        float s = 0.f;
        for (int c = lane; c < Mm; c += 32) {
            float v = g_mem[(size_t)n * Mm + c];
            s += v * v;
        }
        s = warpReduceSum(s);
        if (lane == 0) g_invmem[n] = 1.f / (sqrtf(s) + 1e-8f);
    }
}
static __device__ __noinline__ void scalars_item(int i)
{
    int head = i >> 3, rb = i & 7;
    const float* p = head ? g_pr : g_pw;
    float* sc = head ? g_scr : g_scw;
    int w = threadIdx.x >> 5, lane = threadIdx.x & 31;
    for (int rr = w; rr < 32; rr += 8) {
        int b = rb * 32 + rr;
        const float* row = p + (size_t)b * (Mm + 6);
        float s = 0.f;
        for (int c = lane; c < Mm; c += 32) {
            float v = row[c];
            s += v * v;
        }
        s = warpReduceSum(s);
        if (lane == 0) {
            sc[b * 8 + 0] = softplus_(row[Mm + 0]);
            sc[b * 8 + 1] = sigm(row[Mm + 1]);
            float s0 = row[Mm + 2], s1 = row[Mm + 3], s2 = row[Mm + 4];
            float mx = fmaxf(s0, fmaxf(s1, s2));
            float e0 = __expf(s0 - mx), e1 = __expf(s1 - mx), e2 = __expf(s2 - mx);
            float inv = 1.f / (e0 + e1 + e2);
            sc[b * 8 + 2] = e0 * inv;
            sc[b * 8 + 3] = e1 * inv;
            sc[b * 8 + 4] = e2 * inv;
            sc[b * 8 + 5] = 1.f + softplus_(row[Mm + 5]);
            sc[b * 8 + 6] = 1.f / (sqrtf(s) + 1e-8f);
        }
    }
}
static __device__ __noinline__ void tail_item(int it, float* shb)
{
    float* wg = shb;
    int b = it & 255, head = it >> 8;
    const float* sim = head ? g_simr : g_simw;
    float* wv = head ? g_wr : g_ww;
    const float* sc = head ? g_scr : g_scw;
    int tid = threadIdx.x;
    float beta = sc[b * 8 + 0], g = sc[b * 8 + 1];
    float s0 = sc[b * 8 + 2], s1 = sc[b * 8 + 3], s2 = sc[b * 8 + 4];
    float gamma = sc[b * 8 + 5], invk = sc[b * 8 + 6];
    float scale = beta * invk;

    float v[4];
    float mx = -3.4e38f;
    #pragma unroll
    for (int i = 0; i < 4; i++) {
        int n = tid + i * 256;
        float t = sim[(size_t)b * Nn + n] * scale * g_invmem[n];
        v[i] = t;
        mx = fmaxf(mx, t);
    }
    mx = blockReduceMax256(mx);
    float s = 0.f;
    #pragma unroll
    for (int i = 0; i < 4; i++) { v[i] = __expf(v[i] - mx); s += v[i]; }
    s = blockReduceSum256(s);
    float invs = 1.f / s;
    #pragma unroll
    for (int i = 0; i < 4; i++) {
        int n = tid + i * 256;
        wg[n] = g * (v[i] * invs) + (1.f - g) * wv[(size_t)b * Nn + n];
    }
    __syncthreads();
    float wp[4];
    float local = 0.f;
    #pragma unroll
    for (int i = 0; i < 4; i++) {
        int n = tid + i * 256;
        float wt = s0 * wg[(n + 1) & (Nn - 1)] + s1 * wg[n] + s2 * wg[(n - 1) & (Nn - 1)];
        float pv = __powf(wt, gamma);
        wp[i] = pv;
        local += pv;
    }
    local = blockReduceSum256(local);
    float invt = 1.f / (local + 1e-8f);
    #pragma unroll
    for (int i = 0; i < 4; i++) {
        int n = tid + i * 256;
        wv[(size_t)b * Nn + n] = wp[i] * invt;
    }
    __syncthreads();
}

// ---------------- the persistent kernel ---------------------------------------
__global__ void __launch_bounds__(NTHR, 1) ntm_persistent(
    const float* __restrict__ x,
    const float* __restrict__ mem0, const float* __restrict__ wr0,
    const float* __restrict__ ww0,  const float* __restrict__ h0,
    const float* __restrict__ Wx,   const float* __restrict__ Wr,
    const float* __restrict__ bh,
    const float* __restrict__ Whr,  const float* __restrict__ bhr,
    const float* __restrict__ Whw,  const float* __restrict__ bhw,
    const float* __restrict__ Wea,  const float* __restrict__ bea,
    const float* __restrict__ Wo,   const float* __restrict__ bo,
    float* __restrict__ out)
{
    __shared__ __align__(16) u32 shb[10240];   // 40 KB
    const int tid = threadIdx.x;
    const int gtid = blockIdx.x * NTHR + tid;
    const int gstride = NBLK * NTHR;

    for (int i = gtid; i < Nn * Mm; i += gstride) g_mem[i] = mem0[i];
    for (int i = gtid; i < Bb * Nn; i += gstride) { g_wr[i] = wr0[i]; g_ww[i] = ww0[i]; }
    for (int i = gtid; i < Bb * Hh; i += gstride) g_h[i] = h0[i];
    gridBarrier();

    // P1: ea from h0 (64 tiles)
    for (int it = blockIdx.x; it < 64; it += NBLK) {
        int tm = it >> 4, tn = it & 15;
        tile_gemm(g_h + (size_t)tm * 64 * Hh, Hh, 1, 0, Wea, 2 * Mm, true, bea,
                  g_ea + (size_t)tm * 64 * (2 * Mm), 2 * Mm, tn * 64, 2 * Mm, Hh, 4, shb);
    }
    gridBarrier();

    for (int t = 0; t < Tt; t++) {
        // B: memupd (128) + out_{t-1} tiles 0..19
        for (int it = blockIdx.x; it < 148; it += NBLK) {
            if (it < 128) tile_memupd(it >> 3, it & 7, shb);
            else if (t > 0) {
                int o = it - 128, tm = o >> 3, tn = o & 7;
                tile_gemm(g_h + (size_t)tm * 64 * Hh, Hh, 1, 0, Wo, Oo, true, bo,
                          out + (size_t)(t - 1) * Oo + (size_t)tm * 64 * Tt * Oo,
                          (size_t)Tt * Oo, tn * 64, Oo, Hh, 2, shb);
            }
        }
        gridBarrier();

        // C: r split-K (128) + invnorm (8) + out_{t-1} tiles 20..31
        for (int it = blockIdx.x; it < 148; it += NBLK) {
            if (it < 128) {
                int c = it >> 5, rest = it & 31, tm = rest >> 3, tn = rest & 7;
                tile_gemm(g_wr + (size_t)tm * 64 * Nn + c * 256, Nn, 1, 0,
                          g_mem + (size_t)c * 256 * Mm, Mm, true, nullptr,
                          g_rpart + (size_t)c * BM + (size_t)tm * 64 * Mm, Mm,
                          tn * 64, Mm, 256, 0, shb);
            } else if (it < 136) invnorm_item(it - 128);
            else if (t > 0) {
                int o = it - 136 + 20, tm = o >> 3, tn = o & 7;
                tile_gemm(g_h + (size_t)tm * 64 * Hh, Hh, 1, 0, Wo, Oo, true, bo,
                          out + (size_t)(t - 1) * Oo + (size_t)tm * 64 * Tt * Oo,
                          (size_t)Tt * Oo, tn * 64, Oo, Hh, 2, shb);
            }
        }
        gridBarrier();

        // D: controller split-K (128): chunks 0,1 x halves; 2,3 r halves
        for (int it = blockIdx.x; it < 128; it += NBLK) {
            int c = it >> 5, rest = it & 31, tm = rest >> 3, tn = rest & 7;
            const float* W = (c < 2) ? (Wx + (size_t)c * 256 * Hh)
                                     : (Wr + (size_t)(c - 2) * 256 * Hh);
            const float* A; int ns; size_t sstr, lda;
            if (c < 2) { A = x + (size_t)t * Ii + (size_t)tm * 64 * Tt * Ii + c * 256;
                         ns = 1; sstr = 0; lda = (size_t)Tt * Ii; }
            else       { A = g_rpart + (size_t)tm * 64 * Mm + (c - 2) * 256;
                         ns = 4; sstr = BM; lda = Mm; }
            tile_gemm(A, lda, ns, sstr, W, Hh, true, nullptr,
                      g_hpart + (size_t)c * BH + (size_t)tm * 64 * Hh, Hh,
                      tn * 64, Hh, 256, 0, shb);
        }
        gridBarrier();

        // D2: h = tanh(sum hpart + bh)
        for (int i = gtid; i < BH; i += gstride)
            g_h[i] = tanh_f(g_hpart[i] + g_hpart[i + BH] + g_hpart[i + 2 * BH]
                            + g_hpart[i + 3 * BH] + bh[i & 511]);
        gridBarrier();

        // E: pw(36) + pr(36) + ea-next(64) = 136
        for (int it = blockIdx.x; it < 136; it += NBLK) {
            if (it < 72) {
                int head = it >= 36, i2 = head ? it - 36 : it;
                int tm = i2 / 9, tn = i2 % 9;
                const float* W = head ? Whr : Whw;
                const float* bb = head ? bhr : bhw;
                float* P = head ? g_pr : g_pw;
                tile_gemm(g_h + (size_t)tm * 64 * Hh, Hh, 1, 0, W, Mm + 6, true, bb,
                          P + (size_t)tm * 64 * (Mm + 6), Mm + 6, tn * 64, Mm + 6,
                          Hh, 3, shb);
            } else {
                int i2 = it - 72, tm = i2 >> 4, tn = i2 & 15;
                tile_gemm(g_h + (size_t)tm * 64 * Hh, Hh, 1, 0, Wea, 2 * Mm, true, bea,
                          g_ea + (size_t)tm * 64 * (2 * Mm), 2 * Mm, tn * 64, 2 * Mm,
                          Hh, 4, shb);
            }
        }
        gridBarrier();

        // F: simw(64) simr(64) NT + head scalars(16)
        for (int it = blockIdx.x; it < 144; it += NBLK) {
            if (it < 128) {
                int head = it >= 64, i2 = head ? it - 64 : it;
                int tm = i2 >> 4, tn = i2 & 15;
                const float* P = head ? g_pr : g_pw;
                float* S = head ? g_simr : g_simw;
                tile_gemm(P + (size_t)tm * 64 * (Mm + 6), Mm + 6, 1, 0,
                          g_mem, Mm, false, nullptr,
                          S + (size_t)tm * 64 * Nn, Nn, tn * 64, Nn, Mm, 0, shb);
            } else scalars_item(it - 128);
        }
        gridBarrier();

        // G: address tails (512 rows)
        for (int it = blockIdx.x; it < 512; it += NBLK)
            tail_item(it, (float*)shb);
        gridBarrier();
    }

    // final out for t = 127
    for (int it = blockIdx.x; it < 32; it += NBLK) {
        int tm = it >> 3, tn = it & 7;
        tile_gemm(g_h + (size_t)tm * 64 * Hh, Hh, 1, 0, Wo, Oo, true, bo,
                  out + (size_t)(Tt - 1) * Oo + (size_t)tm * 64 * Tt * Oo,
                  (size_t)Tt * Oo, tn * 64, Oo, Hh, 2, shb);
    }
}

// ---------------- host --------------------------------------------------------
extern "C" void kernel_launch(void* const* d_in, const int* in_sizes, int n_in,
                              void* d_out, int out_size)
{
    const float* x    = (const float*)d_in[0];
    const float* mem0 = (const float*)d_in[1];
    const float* wr0  = (const float*)d_in[2];
    const float* ww0  = (const float*)d_in[3];
    const float* h0   = (const float*)d_in[4];
    const float* Wx   = (const float*)d_in[5];
    const float* Wr   = (const float*)d_in[6];
    const float* bh   = (const float*)d_in[7];
    const float* Whr  = (const float*)d_in[8];
    const float* bhr  = (const float*)d_in[9];
    const float* Whw  = (const float*)d_in[10];
    const float* bhw  = (const float*)d_in[11];
    const float* Wea  = (const float*)d_in[12];
    const float* bea  = (const float*)d_in[13];
    const float* Wo   = (const float*)d_in[14];
    const float* bo   = (const float*)d_in[15];
    float* out = (float*)d_out;

    ntm_persistent<<<NBLK, NTHR>>>(x, mem0, wr0, ww0, h0, Wx, Wr, bh,
                                   Whr, bhr, Whw, bhw, Wea, bea, Wo, bo, out);
}

// round 10
// speedup vs baseline: 1.4700x; 1.1858x over previous
#include <cuda_runtime.h>
#include <math.h>

#define Bb 256
#define Tt 128
#define Ii 512
#define Hh 512
#define Nn 1024
#define Mm 512
#define Oo 512
#define NBLK 148
#define NTHR 256
#define BH (Bb * Hh)
#define BM (Bb * Mm)

typedef unsigned int u32;

// plane sizes (u32)
#define PSZ_WT 131072u   // 512x256
#define PSZ_WH 147456u   // 576x256
#define PSZ_WEA 262144u  // 1024x256
#define PSZ_H 65536u     // 256x256
#define PSZ_K 65536u
#define PSZ_WR 131072u   // 256x512
#define PSZ_MEM 262144u  // 1024x256
#define PSZ_X 8388608u   // 256x32768

__device__ float g_mem[Nn * Mm];
__device__ float g_wr[Bb * Nn];
__device__ float g_ww[Bb * Nn];
__device__ float g_h[Bb * Hh];
__device__ float g_ea[Bb * 2 * Mm];
__device__ float g_rpart[4 * Bb * Mm];
__device__ float g_hpart[4 * Bb * Hh];
__device__ float g_pw[Bb * (Mm + 6)];
__device__ float g_pr[Bb * (Mm + 6)];
__device__ float g_scw[Bb * 8];
__device__ float g_scr[Bb * 8];
__device__ float g_simw[Bb * Nn];
__device__ float g_simr[Bb * Nn];
__device__ float g_invmem[Nn];
__device__ unsigned g_bar_count;
__device__ unsigned g_bar_gen;

// bf16 hi/lo planes (lo at +PSZ)
__device__ u32 pWxT[2 * PSZ_WT];
__device__ u32 pWrT[2 * PSZ_WT];
__device__ u32 pWoT[2 * PSZ_WT];
__device__ u32 pWhwT[2 * PSZ_WH];
__device__ u32 pWhrT[2 * PSZ_WH];
__device__ u32 pWeaT[2 * PSZ_WEA];
__device__ u32 pH[2 * PSZ_H];
__device__ u32 pKw[2 * PSZ_K];
__device__ u32 pKr[2 * PSZ_K];
__device__ u32 pWrp[2 * PSZ_WR];
__device__ u32 pMem[2 * PSZ_MEM];
__device__ u32 pX[2 * PSZ_X];

static __device__ __forceinline__ void gridBarrier() {
    __syncthreads();
    __threadfence();
    if (threadIdx.x == 0) {
        unsigned gen = *(volatile unsigned*)&g_bar_gen;
        unsigned prev = atomicAdd(&g_bar_count, 1u);
        if (prev == NBLK - 1) {
            g_bar_count = 0;
            __threadfence();
            *(volatile unsigned*)&g_bar_gen = gen + 1;
        } else {
            while (*(volatile unsigned*)&g_bar_gen == gen) { __nanosleep(64); }
        }
    }
    __syncthreads();
}

// ---------------- math helpers ----------------------------------------------
static __device__ __forceinline__ float sigm(float x) { return 1.f / (1.f + __expf(-x)); }
static __device__ __forceinline__ float tanh_f(float x) {
    float t = __expf(-2.f * fabsf(x));
    float r = (1.f - t) / (1.f + t);
    return copysignf(r, x);
}
static __device__ __forceinline__ float softplus_(float x) {
    return fmaxf(x, 0.f) + log1pf(__expf(-fabsf(x)));
}
static __device__ __forceinline__ float warpReduceSum(float v) {
    #pragma unroll
    for (int o = 16; o > 0; o >>= 1) v += __shfl_xor_sync(0xffffffffu, v, o);
    return v;
}
static __device__ __forceinline__ float warpReduceMax(float v) {
    #pragma unroll
    for (int o = 16; o > 0; o >>= 1) v = fmaxf(v, __shfl_xor_sync(0xffffffffu, v, o));
    return v;
}
static __device__ __forceinline__ float blockReduceSum256(float v) {
    __shared__ float sh[8];
    int lane = threadIdx.x & 31, wid = threadIdx.x >> 5;
    v = warpReduceSum(v);
    if (lane == 0) sh[wid] = v;
    __syncthreads();
    if (wid == 0) {
        float t = (lane < 8) ? sh[lane] : 0.f;
        t = warpReduceSum(t);
        if (lane == 0) sh[0] = t;
    }
    __syncthreads();
    float r = sh[0];
    __syncthreads();
    return r;
}
static __device__ __forceinline__ float blockReduceMax256(float v) {
    __shared__ float sh[8];
    int lane = threadIdx.x & 31, wid = threadIdx.x >> 5;
    v = warpReduceMax(v);
    if (lane == 0) sh[wid] = v;
    __syncthreads();
    if (wid == 0) {
        float t = (lane < 8) ? sh[lane] : -3.4e38f;
        t = warpReduceMax(t);
        if (lane == 0) sh[0] = t;
    }
    __syncthreads();
    float r = sh[0];
    __syncthreads();
    return r;
}

// ---------------- bf16 split + mma -------------------------------------------
static __device__ __forceinline__ void split2(float x0, float x1, u32 &hi, u32 &lo) {
    u32 h;
    asm("cvt.rn.bf16x2.f32 %0, %1, %2;" : "=r"(h) : "f"(x1), "f"(x0));
    float h0 = __uint_as_float(h << 16);
    float h1 = __uint_as_float(h & 0xffff0000u);
    asm("cvt.rn.bf16x2.f32 %0, %1, %2;" : "=r"(lo) : "f"(x1 - h1), "f"(x0 - h0));
    hi = h;
}
static __device__ __forceinline__ void mma16816(float* c,
    u32 a0, u32 a1, u32 a2, u32 a3, u32 b0, u32 b1)
{
    asm("mma.sync.aligned.m16n8k16.row.col.f32.bf16.bf16.f32 "
        "{%0,%1,%2,%3},{%4,%5,%6,%7},{%8,%9},{%0,%1,%2,%3};"
        : "+f"(c[0]), "+f"(c[1]), "+f"(c[2]), "+f"(c[3])
        : "r"(a0), "r"(a1), "r"(a2), "r"(a3), "r"(b0), "r"(b1));
}

// ---------------- cvt staging (R9, kept for memupd / mem / rpart) ------------
struct StR { float2 v[2]; };
static __device__ __forceinline__ StR load_rows(const float* __restrict__ A,
    size_t lda, int k0, int nsum, size_t sstr)
{
    int t = threadIdx.x;
    int row = t >> 2, w = t & 3;
    const float* p = A + (size_t)row * lda + k0 + 2 * w;
    StR s;
    #pragma unroll
    for (int i = 0; i < 2; i++) {
        float2 v = *(const float2*)(p + 8 * i);
        if (nsum == 4) {
            #pragma unroll
            for (int q = 1; q < 4; q++) {
                float2 u = *(const float2*)(p + 8 * i + q * sstr);
                v.x += u.x; v.y += u.y;
            }
        }
        s.v[i] = v;
    }
    return s;
}
static __device__ __forceinline__ void store_rows(StR s, u32* sm) {
    int t = threadIdx.x;
    int row = t >> 2, w = t & 3;
    #pragma unroll
    for (int i = 0; i < 2; i++) {
        u32 hi, lo;
        split2(s.v[i].x, s.v[i].y, hi, lo);
        sm[row * 20 + w + 4 * i] = hi;
        sm[1280 + row * 20 + w + 4 * i] = lo;
    }
}
struct StT { float v[4]; };
static __device__ __forceinline__ StT load_T(const float* __restrict__ W,
    size_t ldw, int cb, int Nc, int k0)
{
    int t = threadIdx.x;
    int p = t >> 5, n0 = t & 31;
    const float* r0 = W + (size_t)(k0 + 2 * p) * ldw + cb;
    StT s;
    #pragma unroll
    for (int i = 0; i < 2; i++) {
        int n = n0 + 32 * i;
        float v0 = 0.f, v1 = 0.f;
        if (cb + n < Nc) { v0 = r0[n]; v1 = r0[ldw + n]; }
        s.v[2 * i] = v0; s.v[2 * i + 1] = v1;
    }
    return s;
}
static __device__ __forceinline__ void store_T(StT s, u32* sm) {
    int t = threadIdx.x;
    int p = t >> 5, n0 = t & 31;
    #pragma unroll
    for (int i = 0; i < 2; i++) {
        int n = n0 + 32 * i;
        u32 hi, lo;
        split2(s.v[2 * i], s.v[2 * i + 1], hi, lo);
        sm[n * 20 + p] = hi;
        sm[1280 + n * 20 + p] = lo;
    }
}

// ---------------- warp compute for one k16 chunk (R9, proven) -----------------
static __device__ __forceinline__ void mma_chunk(const u32* As, const u32* Bs,
    int wm, int wn, int lane, float acc[4][4])
{
    int r = lane >> 2, w = lane & 3;
    const u32* Ah = As + (wm * 16 + r) * 20 + w;
    u32 a0 = Ah[0], a1 = Ah[160], a2 = Ah[4], a3 = Ah[164];
    u32 e0 = Ah[1280], e1 = Ah[1440], e2 = Ah[1284], e3 = Ah[1444];
    #pragma unroll
    for (int j = 0; j < 4; j++) {
        const u32* Bh = Bs + (wn * 32 + j * 8 + r) * 20 + w;
        u32 b0 = Bh[0], b1 = Bh[4];
        u32 f0 = Bh[1280], f1 = Bh[1284];
        mma16816(acc[j], a0, a1, a2, a3, b0, b1);
        mma16816(acc[j], a0, a1, a2, a3, f0, f1);
        mma16816(acc[j], e0, e1, e2, e3, b0, b1);
    }
}

// ---------------- generic 64x64 GEMM tile, distance-2 pipeline ----------------
// A: aPl != 0 -> copy planes (aPl pre-offset to row0+koff, lo at +apsz, row stride arw)
//    aPl == 0 -> rows-sum4 cvt from (aF, lda, sstr)
// B: bPl != 0 -> copy planes (pre-offset to bn row + koff)
//    bPl == 0 -> transpose-cvt from fp32 (bF pre-offset to col bn, ld ldb)
// kPl: emit bf16 key planes for cols<512 (pre-offset to row0), lo at +kpsz
static __device__ void tile_gemm(
    const u32* aPl, size_t arw, size_t apsz,
    const float* aF, size_t lda, size_t sstr,
    const u32* bPl, size_t brw, size_t bpsz,
    const float* bF, size_t ldb,
    const float* bias, float* C, size_t ldc,
    int bn, int Nc, int K, int act,
    u32* kPl, size_t kpsz, u32* shb)
{
    const int lane = threadIdx.x & 31, wid = threadIdx.x >> 5;
    const int wm = wid & 3, wn = wid >> 2;
    const int t = threadIdx.x;
    const int crow = t >> 2, cg = (t & 3) * 2;
    float acc[4][4] = {};
    u32* Ab[2] = {shb, shb + 2560};
    u32* Bf[2] = {shb + 5120, shb + 7680};
    const u32* aH = aPl ? aPl + (size_t)crow * arw + cg : (const u32*)0;
    const u32* bH = bPl ? bPl + (size_t)crow * brw + cg : (const u32*)0;

    uint2 rA[2][2], rB[2][2];
    StR sA[2]; StT sB[2];
    const int NC = K >> 4;

    #define LDA_(s, ci) { if (aPl) { rA[s][0] = *(const uint2*)(aH + (size_t)(ci) * 8); \
                                     rA[s][1] = *(const uint2*)(aH + apsz + (size_t)(ci) * 8); } \
                          else sA[s] = load_rows(aF, lda, (ci) * 16, 4, sstr); }
    #define LDB_(s, ci) { if (bPl) { rB[s][0] = *(const uint2*)(bH + (size_t)(ci) * 8); \
                                     rB[s][1] = *(const uint2*)(bH + bpsz + (size_t)(ci) * 8); } \
                          else sB[s] = load_T(bF, ldb, 0, 1 << 30, (ci) * 16); }
    #define STA_(s, b) { if (aPl) { *(uint2*)(Ab[b] + crow * 20 + cg) = rA[s][0]; \
                                    *(uint2*)(Ab[b] + 1280 + crow * 20 + cg) = rA[s][1]; } \
                         else store_rows(sA[s], Ab[b]); }
    #define STB_(s, b) { if (bPl) { *(uint2*)(Bf[b] + crow * 20 + cg) = rB[s][0]; \
                                    *(uint2*)(Bf[b] + 1280 + crow * 20 + cg) = rB[s][1]; } \
                         else store_T(sB[s], Bf[b]); }

    LDA_(0, 0) LDB_(0, 0)
    LDA_(1, 1) LDB_(1, 1)
    STA_(0, 0) STB_(0, 0)
    __syncthreads();
    for (int i = 0; i < NC; i++) {
        mma_chunk(Ab[i & 1], Bf[i & 1], wm, wn, lane, acc);
        if (i + 2 < NC) { LDA_(i & 1, i + 2) LDB_(i & 1, i + 2) }
        if (i + 1 < NC) {
            STA_((i + 1) & 1, (i + 1) & 1) STB_((i + 1) & 1, (i + 1) & 1)
            __syncthreads();
        }
    }
    // epilogue
    int r = lane >> 2, c2 = (lane & 3) * 2;
    #pragma unroll
    for (int j = 0; j < 4; j++) {
        int col0 = bn + wn * 32 + j * 8 + c2;
        #pragma unroll
        for (int rr = 0; rr < 2; rr++) {
            int row = wm * 16 + r + rr * 8;
            float v0 = acc[j][rr * 2 + 0], v1 = acc[j][rr * 2 + 1];
            bool ok0 = col0 < Nc, ok1 = (col0 + 1) < Nc;
            if (bias) { if (ok0) v0 += bias[col0]; if (ok1) v1 += bias[col0 + 1]; }
            if (act == 2) { v0 = sigm(v0); v1 = sigm(v1); }
            else if (act == 3) { if (col0 < 512) { v0 = tanh_f(v0); v1 = tanh_f(v1); } }
            else if (act == 4) {
                if (col0 < 512) { v0 = sigm(v0); v1 = sigm(v1); }
                else { v0 = tanh_f(v0); v1 = tanh_f(v1); }
            }
            if (ok0) C[(size_t)row * ldc + col0] = v0;
            if (ok1) C[(size_t)row * ldc + col0 + 1] = v1;
            if (kPl && col0 < 512) {
                u32 hi, lo;
                split2(v0, v1, hi, lo);
                kPl[(size_t)row * 256 + (col0 >> 1)] = hi;
                kPl[kpsz + (size_t)row * 256 + (col0 >> 1)] = lo;
            }
        }
    }
}

// ---------------- memupd tile (R9 + memP emit) --------------------------------
static __device__ void tile_memupd(int tn, int tm, u32* shb)
{
    const int lane = threadIdx.x & 31, wid = threadIdx.x >> 5;
    const int wm = wid & 3, wn = wid >> 2;
    const int bnrow = tn * 64, bmcol = tm * 64;
    u32* Wb = shb;
    u32* Eb = shb + 2560;
    u32* Ab = shb + 5120;
    float acce[4][4] = {};
    float acca[4][4] = {};

    {
        StT sw = load_T(g_ww, Nn, bnrow, 1 << 30, 0);
        StT se = load_T(g_ea, 2 * Mm, bmcol, 1 << 30, 0);
        StT sv = load_T(g_ea, 2 * Mm, Mm + bmcol, 1 << 30, 0);
        store_T(sw, Wb); store_T(se, Eb); store_T(sv, Ab);
    }
    __syncthreads();
    for (int k0 = 0; k0 < Bb; k0 += 16) {
        StT sw, se, sv;
        bool more = (k0 + 16 < Bb);
        if (more) {
            sw = load_T(g_ww, Nn, bnrow, 1 << 30, k0 + 16);
            se = load_T(g_ea, 2 * Mm, bmcol, 1 << 30, k0 + 16);
            sv = load_T(g_ea, 2 * Mm, Mm + bmcol, 1 << 30, k0 + 16);
        }
        {
            int r = lane >> 2, w = lane & 3;
            const u32* Ah = Wb + (wm * 16 + r) * 20 + w;
            u32 a0 = Ah[0], a1 = Ah[160], a2 = Ah[4], a3 = Ah[164];
            u32 e0 = Ah[1280], e1 = Ah[1440], e2 = Ah[1284], e3 = Ah[1444];
            #pragma unroll
            for (int j = 0; j < 4; j++) {
                const u32* Bh = Eb + (wn * 32 + j * 8 + r) * 20 + w;
                u32 b0 = Bh[0], b1 = Bh[4], f0 = Bh[1280], f1 = Bh[1284];
                mma16816(acce[j], a0, a1, a2, a3, b0, b1);
                mma16816(acce[j], a0, a1, a2, a3, f0, f1);
                mma16816(acce[j], e0, e1, e2, e3, b0, b1);
                const u32* Ch = Ab + (wn * 32 + j * 8 + r) * 20 + w;
                u32 g0 = Ch[0], g1 = Ch[4], h0 = Ch[1280], h1 = Ch[1284];
                mma16816(acca[j], a0, a1, a2, a3, g0, g1);
                mma16816(acca[j], a0, a1, a2, a3, h0, h1);
                mma16816(acca[j], e0, e1, e2, e3, g0, g1);
            }
        }
        __syncthreads();
        if (more) {
            store_T(sw, Wb); store_T(se, Eb); store_T(sv, Ab);
        }
        __syncthreads();
    }
    const float invB = 1.f / (float)Bb;
    int r = lane >> 2, c2 = (lane & 3) * 2;
    #pragma unroll
    for (int j = 0; j < 4; j++) {
        int m0 = bmcol + wn * 32 + j * 8 + c2;
        #pragma unroll
        for (int rr = 0; rr < 2; rr++) {
            int n = bnrow + wm * 16 + r + rr * 8;
            float e0v = acce[j][rr * 2 + 0], e1v = acce[j][rr * 2 + 1];
            float a0v = acca[j][rr * 2 + 0], a1v = acca[j][rr * 2 + 1];
            float o0 = g_mem[(size_t)n * Mm + m0];
            float o1 = g_mem[(size_t)n * Mm + m0 + 1];
            float nv0 = o0 * (1.f - e0v * invB) + a0v * invB;
            float nv1 = o1 * (1.f - e1v * invB) + a1v * invB;
            g_mem[(size_t)n * Mm + m0] = nv0;
            g_mem[(size_t)n * Mm + m0 + 1] = nv1;
            u32 hi, lo;
            split2(nv0, nv1, hi, lo);
            pMem[(size_t)n * 256 + (m0 >> 1)] = hi;
            pMem[PSZ_MEM + (size_t)n * 256 + (m0 >> 1)] = lo;
        }
    }
}

// ---------------- small row-wise items ----------------------------------------
static __device__ __noinline__ void invnorm_item(int item)
{
    int w = threadIdx.x >> 5, lane = threadIdx.x & 31;
    for (int rr = w; rr < 128; rr += 8) {
        int n = item * 128 + rr;
        float s = 0.f;
        for (int c = lane; c < Mm; c += 32) {
            float v = g_mem[(size_t)n * Mm + c];
            s += v * v;
        }
        s = warpReduceSum(s);
        if (lane == 0) g_invmem[n] = 1.f / (sqrtf(s) + 1e-8f);
    }
}
static __device__ __noinline__ void scalars_item(int i)
{
    int head = i >> 3, rb = i & 7;
    const float* p = head ? g_pr : g_pw;
    float* sc = head ? g_scr : g_scw;
    int w = threadIdx.x >> 5, lane = threadIdx.x & 31;
    for (int rr = w; rr < 32; rr += 8) {
        int b = rb * 32 + rr;
        const float* row = p + (size_t)b * (Mm + 6);
        float s = 0.f;
        for (int c = lane; c < Mm; c += 32) {
            float v = row[c];
            s += v * v;
        }
        s = warpReduceSum(s);
        if (lane == 0) {
            sc[b * 8 + 0] = softplus_(row[Mm + 0]);
            sc[b * 8 + 1] = sigm(row[Mm + 1]);
            float s0 = row[Mm + 2], s1 = row[Mm + 3], s2 = row[Mm + 4];
            float mx = fmaxf(s0, fmaxf(s1, s2));
            float e0 = __expf(s0 - mx), e1 = __expf(s1 - mx), e2 = __expf(s2 - mx);
            float inv = 1.f / (e0 + e1 + e2);
            sc[b * 8 + 2] = e0 * inv;
            sc[b * 8 + 3] = e1 * inv;
            sc[b * 8 + 4] = e2 * inv;
            sc[b * 8 + 5] = 1.f + softplus_(row[Mm + 5]);
            sc[b * 8 + 6] = 1.f / (sqrtf(s) + 1e-8f);
        }
    }
}

// -------- fused address tail; head==1 (wr) also emits wrP planes --------------
static __device__ __noinline__ void tail_item(int it, float* shb)
{
    float* wg = shb;
    int b = it & 255, head = it >> 8;
    const float* sim = head ? g_simr : g_simw;
    float* wv = head ? g_wr : g_ww;
    const float* sc = head ? g_scr : g_scw;
    int tid = threadIdx.x;
    int nb = tid * 4;
    float beta = sc[b * 8 + 0], g = sc[b * 8 + 1];
    float s0 = sc[b * 8 + 2], s1 = sc[b * 8 + 3], s2 = sc[b * 8 + 4];
    float gamma = sc[b * 8 + 5], invk = sc[b * 8 + 6];
    float scale = beta * invk;

    float4 sv = *(const float4*)&sim[(size_t)b * Nn + nb];
    float4 iv = *(const float4*)&g_invmem[nb];
    float v[4] = {sv.x * scale * iv.x, sv.y * scale * iv.y,
                  sv.z * scale * iv.z, sv.w * scale * iv.w};
    float mx = fmaxf(fmaxf(v[0], v[1]), fmaxf(v[2], v[3]));
    mx = blockReduceMax256(mx);
    float s = 0.f;
    #pragma unroll
    for (int i = 0; i < 4; i++) { v[i] = __expf(v[i] - mx); s += v[i]; }
    s = blockReduceSum256(s);
    float invs = 1.f / s;
    float4 wp4 = *(const float4*)&wv[(size_t)b * Nn + nb];
    float wpv[4] = {wp4.x, wp4.y, wp4.z, wp4.w};
    #pragma unroll
    for (int i = 0; i < 4; i++)
        wg[nb + i] = g * (v[i] * invs) + (1.f - g) * wpv[i];
    __syncthreads();
    float o[4];
    float local = 0.f;
    #pragma unroll
    for (int i = 0; i < 4; i++) {
        int n = nb + i;
        float wt = s0 * wg[(n + 1) & (Nn - 1)] + s1 * wg[n] + s2 * wg[(n - 1) & (Nn - 1)];
        float pv = __powf(wt, gamma);
        o[i] = pv;
        local += pv;
    }
    local = blockReduceSum256(local);
    float invt = 1.f / (local + 1e-8f);
    #pragma unroll
    for (int i = 0; i < 4; i++) o[i] *= invt;
    *(float4*)&wv[(size_t)b * Nn + nb] = make_float4(o[0], o[1], o[2], o[3]);
    if (head) {
        u32 h0, l0, h1, l1;
        split2(o[0], o[1], h0, l0);
        split2(o[2], o[3], h1, l1);
        size_t kw = (size_t)b * 512 + (nb >> 1);
        pWrp[kw] = h0; pWrp[kw + 1] = h1;
        pWrp[PSZ_WR + kw] = l0; pWrp[PSZ_WR + kw + 1] = l1;
    }
    __syncthreads();
}

// ---------------- P0 converters -----------------------------------------------
// transpose-split: dst[row][kw] from src[k][row]; rows R (pad>=VR zero), 256 kw
static __device__ void conv_T(u32* dst, const float* __restrict__ src,
                              int R, int VR, int ldw, int gtid, int gstride)
{
    size_t psz = (size_t)R * 256;
    for (size_t idx = gtid; idx < psz; idx += gstride) {
        int kw = (int)(idx / R);
        int row = (int)(idx - (size_t)kw * R);
        float v0 = 0.f, v1 = 0.f;
        if (row < VR) {
            v0 = src[(size_t)(2 * kw) * ldw + row];
            v1 = src[(size_t)(2 * kw + 1) * ldw + row];
        }
        u32 hi, lo;
        split2(v0, v1, hi, lo);
        dst[(size_t)row * 256 + kw] = hi;
        dst[psz + (size_t)row * 256 + kw] = lo;
    }
}
// linear pair-split: dst[i] from src[2i],src[2i+1]
static __device__ void conv_P(u32* dst, const float* __restrict__ src,
                              size_t npairs, size_t psz, int gtid, int gstride)
{
    for (size_t i = gtid; i < npairs; i += gstride) {
        float2 v = *(const float2*)(src + 2 * i);
        u32 hi, lo;
        split2(v.x, v.y, hi, lo);
        dst[i] = hi;
        dst[psz + i] = lo;
    }
}

// ---------------- the persistent kernel ---------------------------------------
__global__ void __launch_bounds__(NTHR, 1) ntm_persistent(
    const float* __restrict__ x,
    const float* __restrict__ mem0, const float* __restrict__ wr0,
    const float* __restrict__ ww0,  const float* __restrict__ h0,
    const float* __restrict__ Wx,   const float* __restrict__ Wr,
    const float* __restrict__ bh,
    const float* __restrict__ Whr,  const float* __restrict__ bhr,
    const float* __restrict__ Whw,  const float* __restrict__ bhw,
    const float* __restrict__ Wea,  const float* __restrict__ bea,
    const float* __restrict__ Wo,   const float* __restrict__ bo,
    float* __restrict__ out)
{
    __shared__ __align__(16) u32 shb[10240];   // 40 KB
    const int tid = threadIdx.x;
    const int gtid = blockIdx.x * NTHR + tid;
    const int gstride = NBLK * NTHR;

    // P0: fp32 state + all conversions
    for (int i = gtid; i < Nn * Mm; i += gstride) g_mem[i] = mem0[i];
    for (int i = gtid; i < Bb * Nn; i += gstride) { g_wr[i] = wr0[i]; g_ww[i] = ww0[i]; }
    for (int i = gtid; i < Bb * Hh; i += gstride) g_h[i] = h0[i];
    conv_P(pH, h0, PSZ_H, PSZ_H, gtid, gstride);
    conv_P(pWrp, wr0, PSZ_WR, PSZ_WR, gtid, gstride);
    conv_P(pX, x, PSZ_X, PSZ_X, gtid, gstride);
    conv_T(pWxT, Wx, 512, 512, Hh, gtid, gstride);
    conv_T(pWrT, Wr, 512, 512, Hh, gtid, gstride);
    conv_T(pWoT, Wo, 512, 512, Oo, gtid, gstride);
    conv_T(pWhwT, Whw, 576, Mm + 6, Mm + 6, gtid, gstride);
    conv_T(pWhrT, Whr, 576, Mm + 6, Mm + 6, gtid, gstride);
    conv_T(pWeaT, Wea, 1024, 1024, 2 * Mm, gtid, gstride);
    gridBarrier();

    // P1: ea from h0 (64 tiles)
    for (int it = blockIdx.x; it < 64; it += NBLK) {
        int tm = it >> 4, tn = it & 15;
        tile_gemm(pH + (size_t)tm * 64 * 256, 256, PSZ_H, 0, 0, 0,
                  pWeaT + (size_t)tn * 64 * 256, 256, PSZ_WEA, 0, 0,
                  bea, g_ea + (size_t)tm * 64 * (2 * Mm), 2 * Mm,
                  tn * 64, 2 * Mm, Hh, 4, 0, 0, shb);
    }
    gridBarrier();

    for (int t = 0; t < Tt; t++) {
        // B: memupd (128) + out_{t-1} tiles 0..19
        for (int it = blockIdx.x; it < 148; it += NBLK) {
            if (it < 128) tile_memupd(it >> 3, it & 7, shb);
            else if (t > 0) {
                int o = it - 128, tm = o >> 3, tn = o & 7;
                tile_gemm(pH + (size_t)tm * 64 * 256, 256, PSZ_H, 0, 0, 0,
                          pWoT + (size_t)tn * 64 * 256, 256, PSZ_WT, 0, 0,
                          bo, out + (size_t)(t - 1) * Oo + (size_t)tm * 64 * Tt * Oo,
                          (size_t)Tt * Oo, tn * 64, Oo, Hh, 2, 0, 0, shb);
            }
        }
        gridBarrier();

        // C: r split-K (128: A=wrP copy, B=mem cvt) + invnorm(8) + out 20..31
        for (int it = blockIdx.x; it < 148; it += NBLK) {
            if (it < 128) {
                int c = it >> 5, rest = it & 31, tm = rest >> 3, tn = rest & 7;
                tile_gemm(pWrp + (size_t)tm * 64 * 512 + c * 128, 512, PSZ_WR, 0, 0, 0,
                          0, 0, 0, g_mem + (size_t)c * 256 * Mm + tn * 64, Mm,
                          nullptr, g_rpart + (size_t)c * BM + (size_t)tm * 64 * Mm, Mm,
                          tn * 64, 1 << 30, 256, 0, 0, 0, shb);
            } else if (it < 136) invnorm_item(it - 128);
            else if (t > 0) {
                int o = it - 136 + 20, tm = o >> 3, tn = o & 7;
                tile_gemm(pH + (size_t)tm * 64 * 256, 256, PSZ_H, 0, 0, 0,
                          pWoT + (size_t)tn * 64 * 256, 256, PSZ_WT, 0, 0,
                          bo, out + (size_t)(t - 1) * Oo + (size_t)tm * 64 * Tt * Oo,
                          (size_t)Tt * Oo, tn * 64, Oo, Hh, 2, 0, 0, shb);
            }
        }
        gridBarrier();

        // D: controller split-K (128)
        for (int it = blockIdx.x; it < 128; it += NBLK) {
            int c = it >> 5, rest = it & 31, tm = rest >> 3, tn = rest & 7;
            if (c < 2) {
                tile_gemm(pX + (size_t)tm * 64 * 32768 + (size_t)t * 256 + c * 128,
                          32768, PSZ_X, 0, 0, 0,
                          pWxT + (size_t)tn * 64 * 256 + c * 128, 256, PSZ_WT, 0, 0,
                          nullptr, g_hpart + (size_t)c * BH + (size_t)tm * 64 * Hh, Hh,
                          tn * 64, 1 << 30, 256, 0, 0, 0, shb);
            } else {
                tile_gemm(0, 0, 0, g_rpart + (size_t)tm * 64 * Mm + (c - 2) * 256, Mm, BM,
                          pWrT + (size_t)tn * 64 * 256 + (c - 2) * 128, 256, PSZ_WT, 0, 0,
                          nullptr, g_hpart + (size_t)c * BH + (size_t)tm * 64 * Hh, Hh,
                          tn * 64, 1 << 30, 256, 0, 0, 0, shb);
            }
        }
        gridBarrier();

        // D2: h = tanh(sum hpart + bh); emit hP planes
        for (int i = gtid; i < BH / 2; i += gstride) {
            int i2 = 2 * i;
            float a0 = g_hpart[i2] + g_hpart[i2 + BH] + g_hpart[i2 + 2 * BH]
                       + g_hpart[i2 + 3 * BH] + bh[i2 & 511];
            float a1 = g_hpart[i2 + 1] + g_hpart[i2 + 1 + BH] + g_hpart[i2 + 1 + 2 * BH]
                       + g_hpart[i2 + 1 + 3 * BH] + bh[(i2 + 1) & 511];
            float v0 = tanh_f(a0), v1 = tanh_f(a1);
            g_h[i2] = v0; g_h[i2 + 1] = v1;
            u32 hi, lo;
            split2(v0, v1, hi, lo);
            pH[i] = hi; pH[PSZ_H + i] = lo;
        }
        gridBarrier();

        // E: pw(36) + pr(36) + ea-next(64) = 136
        for (int it = blockIdx.x; it < 136; it += NBLK) {
            if (it < 72) {
                int head = it >= 36, i2 = head ? it - 36 : it;
                int tm = i2 / 9, tn = i2 % 9;
                const u32* WT = head ? pWhrT : pWhwT;
                const float* bb = head ? bhr : bhw;
                float* P = head ? g_pr : g_pw;
                u32* kP = head ? pKr : pKw;
                tile_gemm(pH + (size_t)tm * 64 * 256, 256, PSZ_H, 0, 0, 0,
                          WT + (size_t)tn * 64 * 256, 256, PSZ_WH, 0, 0,
                          bb, P + (size_t)tm * 64 * (Mm + 6), Mm + 6,
                          tn * 64, Mm + 6, Hh, 3,
                          kP + (size_t)tm * 64 * 256, PSZ_K, shb);
            } else {
                int i2 = it - 72, tm = i2 >> 4, tn = i2 & 15;
                tile_gemm(pH + (size_t)tm * 64 * 256, 256, PSZ_H, 0, 0, 0,
                          pWeaT + (size_t)tn * 64 * 256, 256, PSZ_WEA, 0, 0,
                          bea, g_ea + (size_t)tm * 64 * (2 * Mm), 2 * Mm,
                          tn * 64, 2 * Mm, Hh, 4, 0, 0, shb);
            }
        }
        gridBarrier();

        // F: simw(64) simr(64) + head scalars(16)
        for (int it = blockIdx.x; it < 144; it += NBLK) {
            if (it < 128) {
                int head = it >= 64, i2 = head ? it - 64 : it;
                int tm = i2 >> 4, tn = i2 & 15;
                const u32* kP = head ? pKr : pKw;
                float* S = head ? g_simr : g_simw;
                tile_gemm(kP + (size_t)tm * 64 * 256, 256, PSZ_K, 0, 0, 0,
                          pMem + (size_t)tn * 64 * 256, 256, PSZ_MEM, 0, 0,
                          nullptr, S + (size_t)tm * 64 * Nn, Nn,
                          tn * 64, 1 << 30, Mm, 0, 0, 0, shb);
            } else scalars_item(it - 128);
        }
        gridBarrier();

        // G: address tails (512 rows)
        for (int it = blockIdx.x; it < 512; it += NBLK)
            tail_item(it, (float*)shb);
        gridBarrier();
    }

    // final out for t = 127
    for (int it = blockIdx.x; it < 32; it += NBLK) {
        int tm = it >> 3, tn = it & 7;
        tile_gemm(pH + (size_t)tm * 64 * 256, 256, PSZ_H, 0, 0, 0,
                  pWoT + (size_t)tn * 64 * 256, 256, PSZ_WT, 0, 0,
                  bo, out + (size_t)(Tt - 1) * Oo + (size_t)tm * 64 * Tt * Oo,
                  (size_t)Tt * Oo, tn * 64, Oo, Hh, 2, 0, 0, shb);
    }
}

// ---------------- host --------------------------------------------------------
extern "C" void kernel_launch(void* const* d_in, const int* in_sizes, int n_in,
                              void* d_out, int out_size)
{
    const float* x    = (const float*)d_in[0];
    const float* mem0 = (const float*)d_in[1];
    const float* wr0  = (const float*)d_in[2];
    const float* ww0  = (const float*)d_in[3];
    const float* h0   = (const float*)d_in[4];
    const float* Wx   = (const float*)d_in[5];
    const float* Wr   = (const float*)d_in[6];
    const float* bh   = (const float*)d_in[7];
    const float* Whr  = (const float*)d_in[8];
    const float* bhr  = (const float*)d_in[9];
    const float* Whw  = (const float*)d_in[10];
    const float* bhw  = (const float*)d_in[11];
    const float* Wea  = (const float*)d_in[12];
    const float* bea  = (const float*)d_in[13];
    const float* Wo   = (const float*)d_in[14];
    const float* bo   = (const float*)d_in[15];
    float* out = (float*)d_out;

    ntm_persistent<<<NBLK, NTHR>>>(x, mem0, wr0, ww0, h0, Wx, Wr, bh,
                                   Whr, bhr, Whw, bhw, Wea, bea, Wo, bo, out);
}

// round 11
// speedup vs baseline: 1.5644x; 1.0642x over previous
#include <cuda_runtime.h>
#include <math.h>

#define Bb 256
#define Tt 128
#define Ii 512
#define Hh 512
#define Nn 1024
#define Mm 512
#define Oo 512
#define NBLK 148
#define NTHR 256
#define BH (Bb * Hh)
#define BM (Bb * Mm)

typedef unsigned int u32;

#define PSZ_WT 131072u
#define PSZ_WH 147456u
#define PSZ_WEA 262144u
#define PSZ_H 65536u
#define PSZ_K 65536u
#define PSZ_WR 131072u
#define PSZ_MEM 262144u
#define PSZ_X 8388608u

__device__ float g_mem[Nn * Mm];
__device__ float g_wr[Bb * Nn];
__device__ float g_ww[Bb * Nn];
__device__ float g_h[Bb * Hh];
__device__ float g_ea[Bb * 2 * Mm];
__device__ float g_rpart[4 * Bb * Mm];
__device__ float g_hpart[4 * Bb * Hh];
__device__ float g_pw[Bb * (Mm + 6)];
__device__ float g_pr[Bb * (Mm + 6)];
__device__ float g_scw[Bb * 8];
__device__ float g_scr[Bb * 8];
__device__ float g_simw[Bb * Nn];
__device__ float g_simr[Bb * Nn];
__device__ float g_invmem[Nn];
__device__ unsigned g_bar_count;
__device__ unsigned g_bar_gen;

__device__ __align__(16) u32 pWxT[2 * PSZ_WT];
__device__ __align__(16) u32 pWrT[2 * PSZ_WT];
__device__ __align__(16) u32 pWoT[2 * PSZ_WT];
__device__ __align__(16) u32 pWhwT[2 * PSZ_WH];
__device__ __align__(16) u32 pWhrT[2 * PSZ_WH];
__device__ __align__(16) u32 pWeaT[2 * PSZ_WEA];
__device__ __align__(16) u32 pH[2 * PSZ_H];
__device__ __align__(16) u32 pKw[2 * PSZ_K];
__device__ __align__(16) u32 pKr[2 * PSZ_K];
__device__ __align__(16) u32 pWrp[2 * PSZ_WR];
__device__ __align__(16) u32 pMem[2 * PSZ_MEM];
__device__ __align__(16) u32 pX[2 * PSZ_X];

static __device__ __forceinline__ void gridBarrier() {
    __syncthreads();
    __threadfence();
    if (threadIdx.x == 0) {
        unsigned gen = *(volatile unsigned*)&g_bar_gen;
        unsigned prev = atomicAdd(&g_bar_count, 1u);
        if (prev == NBLK - 1) {
            g_bar_count = 0;
            __threadfence();
            *(volatile unsigned*)&g_bar_gen = gen + 1;
        } else {
            while (*(volatile unsigned*)&g_bar_gen == gen) { __nanosleep(64); }
        }
    }
    __syncthreads();
}

// ---------------- math helpers ----------------------------------------------
static __device__ __forceinline__ float sigm(float x) { return 1.f / (1.f + __expf(-x)); }
static __device__ __forceinline__ float tanh_f(float x) {
    float t = __expf(-2.f * fabsf(x));
    float r = (1.f - t) / (1.f + t);
    return copysignf(r, x);
}
static __device__ __forceinline__ float softplus_(float x) {
    return fmaxf(x, 0.f) + log1pf(__expf(-fabsf(x)));
}
static __device__ __forceinline__ float warpReduceSum(float v) {
    #pragma unroll
    for (int o = 16; o > 0; o >>= 1) v += __shfl_xor_sync(0xffffffffu, v, o);
    return v;
}
static __device__ __forceinline__ float warpReduceMax(float v) {
    #pragma unroll
    for (int o = 16; o > 0; o >>= 1) v = fmaxf(v, __shfl_xor_sync(0xffffffffu, v, o));
    return v;
}
static __device__ __forceinline__ float blockReduceSum256(float v) {
    __shared__ float sh[8];
    int lane = threadIdx.x & 31, wid = threadIdx.x >> 5;
    v = warpReduceSum(v);
    if (lane == 0) sh[wid] = v;
    __syncthreads();
    if (wid == 0) {
        float t = (lane < 8) ? sh[lane] : 0.f;
        t = warpReduceSum(t);
        if (lane == 0) sh[0] = t;
    }
    __syncthreads();
    float r = sh[0];
    __syncthreads();
    return r;
}
static __device__ __forceinline__ float blockReduceMax256(float v) {
    __shared__ float sh[8];
    int lane = threadIdx.x & 31, wid = threadIdx.x >> 5;
    v = warpReduceMax(v);
    if (lane == 0) sh[wid] = v;
    __syncthreads();
    if (wid == 0) {
        float t = (lane < 8) ? sh[lane] : -3.4e38f;
        t = warpReduceMax(t);
        if (lane == 0) sh[0] = t;
    }
    __syncthreads();
    float r = sh[0];
    __syncthreads();
    return r;
}

// ---------------- bf16 split + mma -------------------------------------------
static __device__ __forceinline__ void split2(float x0, float x1, u32 &hi, u32 &lo) {
    u32 h;
    asm("cvt.rn.bf16x2.f32 %0, %1, %2;" : "=r"(h) : "f"(x1), "f"(x0));
    float h0 = __uint_as_float(h << 16);
    float h1 = __uint_as_float(h & 0xffff0000u);
    asm("cvt.rn.bf16x2.f32 %0, %1, %2;" : "=r"(lo) : "f"(x1 - h1), "f"(x0 - h0));
    hi = h;
}
static __device__ __forceinline__ void mma16816(float* c,
    u32 a0, u32 a1, u32 a2, u32 a3, u32 b0, u32 b1)
{
    asm("mma.sync.aligned.m16n8k16.row.col.f32.bf16.bf16.f32 "
        "{%0,%1,%2,%3},{%4,%5,%6,%7},{%8,%9},{%0,%1,%2,%3};"
        : "+f"(c[0]), "+f"(c[1]), "+f"(c[2]), "+f"(c[3])
        : "r"(a0), "r"(a1), "r"(a2), "r"(a3), "r"(b0), "r"(b1));
}
static __device__ __forceinline__ void cpa16(u32* s, const u32* g) {
    unsigned sa = (unsigned)__cvta_generic_to_shared(s);
    asm volatile("cp.async.ca.shared.global [%0], [%1], 16;" :: "r"(sa), "l"(g));
}

// ---------------- cvt staging (for memupd / mem-T / rpart-sum) ----------------
struct StR { float2 v[2]; };
static __device__ __forceinline__ StR load_rows(const float* __restrict__ A,
    size_t lda, int k0, int nsum, size_t sstr)
{
    int t = threadIdx.x;
    int row = t >> 2, w = t & 3;
    const float* p = A + (size_t)row * lda + k0 + 2 * w;
    StR s;
    #pragma unroll
    for (int i = 0; i < 2; i++) {
        float2 v = *(const float2*)(p + 8 * i);
        if (nsum == 4) {
            #pragma unroll
            for (int q = 1; q < 4; q++) {
                float2 u = *(const float2*)(p + 8 * i + q * sstr);
                v.x += u.x; v.y += u.y;
            }
        }
        s.v[i] = v;
    }
    return s;
}
static __device__ __forceinline__ void store_rows(StR s, u32* sm) {
    int t = threadIdx.x;
    int row = t >> 2, w = t & 3;
    #pragma unroll
    for (int i = 0; i < 2; i++) {
        u32 hi, lo;
        split2(s.v[i].x, s.v[i].y, hi, lo);
        sm[row * 20 + w + 4 * i] = hi;
        sm[1280 + row * 20 + w + 4 * i] = lo;
    }
}
struct StT { float v[4]; };
static __device__ __forceinline__ StT load_T(const float* __restrict__ W,
    size_t ldw, int cb, int Nc, int k0)
{
    int t = threadIdx.x;
    int p = t >> 5, n0 = t & 31;
    const float* r0 = W + (size_t)(k0 + 2 * p) * ldw + cb;
    StT s;
    #pragma unroll
    for (int i = 0; i < 2; i++) {
        int n = n0 + 32 * i;
        float v0 = 0.f, v1 = 0.f;
        if (cb + n < Nc) { v0 = r0[n]; v1 = r0[ldw + n]; }
        s.v[2 * i] = v0; s.v[2 * i + 1] = v1;
    }
    return s;
}
static __device__ __forceinline__ void store_T(StT s, u32* sm) {
    int t = threadIdx.x;
    int p = t >> 5, n0 = t & 31;
    #pragma unroll
    for (int i = 0; i < 2; i++) {
        int n = n0 + 32 * i;
        u32 hi, lo;
        split2(s.v[2 * i], s.v[2 * i + 1], hi, lo);
        sm[n * 20 + p] = hi;
        sm[1280 + n * 20 + p] = lo;
    }
}

// ---------------- warp compute for one k16 chunk ------------------------------
static __device__ __forceinline__ void mma_chunk(const u32* As, const u32* Bs,
    int wm, int wn, int lane, float acc[4][4])
{
    int r = lane >> 2, w = lane & 3;
    const u32* Ah = As + (wm * 16 + r) * 20 + w;
    u32 a0 = Ah[0], a1 = Ah[160], a2 = Ah[4], a3 = Ah[164];
    u32 e0 = Ah[1280], e1 = Ah[1440], e2 = Ah[1284], e3 = Ah[1444];
    #pragma unroll
    for (int j = 0; j < 4; j++) {
        const u32* Bh = Bs + (wn * 32 + j * 8 + r) * 20 + w;
        u32 b0 = Bh[0], b1 = Bh[4];
        u32 f0 = Bh[1280], f1 = Bh[1284];
        mma16816(acc[j], a0, a1, a2, a3, b0, b1);
        mma16816(acc[j], a0, a1, a2, a3, f0, f1);
        mma16816(acc[j], e0, e1, e2, e3, b0, b1);
    }
}

// ---------------- shared epilogue --------------------------------------------
static __device__ __forceinline__ void epilogue(float acc[4][4],
    const float* bias, float* C, size_t ldc, int bn, int Nc, int act,
    u32* kPl, size_t kpsz, int wm, int wn, int lane)
{
    int r = lane >> 2, c2 = (lane & 3) * 2;
    #pragma unroll
    for (int j = 0; j < 4; j++) {
        int col0 = bn + wn * 32 + j * 8 + c2;
        #pragma unroll
        for (int rr = 0; rr < 2; rr++) {
            int row = wm * 16 + r + rr * 8;
            float v0 = acc[j][rr * 2 + 0], v1 = acc[j][rr * 2 + 1];
            bool ok0 = col0 < Nc, ok1 = (col0 + 1) < Nc;
            if (bias) { if (ok0) v0 += bias[col0]; if (ok1) v1 += bias[col0 + 1]; }
            if (act == 2) { v0 = sigm(v0); v1 = sigm(v1); }
            else if (act == 3) { if (col0 < 512) { v0 = tanh_f(v0); v1 = tanh_f(v1); } }
            else if (act == 4) {
                if (col0 < 512) { v0 = sigm(v0); v1 = sigm(v1); }
                else { v0 = tanh_f(v0); v1 = tanh_f(v1); }
            }
            if (ok0) C[(size_t)row * ldc + col0] = v0;
            if (ok1) C[(size_t)row * ldc + col0 + 1] = v1;
            if (kPl && col0 < 512) {
                u32 hi, lo;
                split2(v0, v1, hi, lo);
                kPl[(size_t)row * 256 + (col0 >> 1)] = hi;
                kPl[kpsz + (size_t)row * 256 + (col0 >> 1)] = lo;
            }
        }
    }
}

// ---------------- plane-plane tile: cp.async depth-3, 4 buffers ---------------
static __device__ void tile_pp(
    const u32* aPl, size_t arw, size_t apsz,
    const u32* bPl, size_t brw, size_t bpsz,
    const float* bias, float* C, size_t ldc,
    int bn, int Nc, int K, int act,
    u32* kPl, size_t kpsz, u32* shb)
{
    const int lane = threadIdx.x & 31, wid = threadIdx.x >> 5;
    const int wm = wid & 3, wn = wid >> 2;
    const int t = threadIdx.x;
    const int row = t >> 2, hf = (t >> 1) & 1, pl = t & 1;
    const u32* ga = aPl + (size_t)pl * apsz + (size_t)row * arw + hf * 4;
    const u32* gb = bPl + (size_t)pl * bpsz + (size_t)row * brw + hf * 4;
    const int soff = pl * 1280 + row * 20 + hf * 4;
    float acc[4][4] = {};
    const int NC = K >> 4;

    #define ISS(ci) { u32* bb_ = shb + ((ci) & 3) * 5120;                       \
                      cpa16(bb_ + soff, ga + (size_t)(ci) * 8);                 \
                      cpa16(bb_ + 2560 + soff, gb + (size_t)(ci) * 8);          \
                      asm volatile("cp.async.commit_group;"); }
    ISS(0) ISS(1) ISS(2)
    for (int i = 0; i < NC; i++) {
        asm volatile("cp.async.wait_group 2;");
        __syncthreads();
        if (i + 3 < NC) ISS(i + 3)
        const u32* base = shb + (i & 3) * 5120;
        mma_chunk(base, base + 2560, wm, wn, lane, acc);
    }
    asm volatile("cp.async.wait_group 0;");
    __syncthreads();
    #undef ISS
    epilogue(acc, bias, C, ldc, bn, Nc, act, kPl, kpsz, wm, wn, lane);
}

// ---------------- mixed tile (A plane or cvt-sum, B plane or cvt-T) ----------
static __device__ void tile_gemm(
    const u32* aPl, size_t arw, size_t apsz,
    const float* aF, size_t lda, size_t sstr,
    const u32* bPl, size_t brw, size_t bpsz,
    const float* bF, size_t ldb,
    const float* bias, float* C, size_t ldc,
    int bn, int Nc, int K, int act,
    u32* kPl, size_t kpsz, u32* shb)
{
    const int lane = threadIdx.x & 31, wid = threadIdx.x >> 5;
    const int wm = wid & 3, wn = wid >> 2;
    const int t = threadIdx.x;
    const int crow = t >> 2, cg = (t & 3) * 2;
    float acc[4][4] = {};
    u32* Ab[2] = {shb, shb + 2560};
    u32* Bf[2] = {shb + 5120, shb + 7680};
    const u32* aH = aPl ? aPl + (size_t)crow * arw + cg : (const u32*)0;
    const u32* bH = bPl ? bPl + (size_t)crow * brw + cg : (const u32*)0;

    uint2 rA[2][2], rB[2][2];
    StR sA[2]; StT sB[2];
    const int NC = K >> 4;

    #define LDA_(s, ci) { if (aPl) { rA[s][0] = *(const uint2*)(aH + (size_t)(ci) * 8); \
                                     rA[s][1] = *(const uint2*)(aH + apsz + (size_t)(ci) * 8); } \
                          else sA[s] = load_rows(aF, lda, (ci) * 16, 4, sstr); }
    #define LDB_(s, ci) { if (bPl) { rB[s][0] = *(const uint2*)(bH + (size_t)(ci) * 8); \
                                     rB[s][1] = *(const uint2*)(bH + bpsz + (size_t)(ci) * 8); } \
                          else sB[s] = load_T(bF, ldb, 0, 1 << 30, (ci) * 16); }
    #define STA_(s, b) { if (aPl) { *(uint2*)(Ab[b] + crow * 20 + cg) = rA[s][0]; \
                                    *(uint2*)(Ab[b] + 1280 + crow * 20 + cg) = rA[s][1]; } \
                         else store_rows(sA[s], Ab[b]); }
    #define STB_(s, b) { if (bPl) { *(uint2*)(Bf[b] + crow * 20 + cg) = rB[s][0]; \
                                    *(uint2*)(Bf[b] + 1280 + crow * 20 + cg) = rB[s][1]; } \
                         else store_T(sB[s], Bf[b]); }

    LDA_(0, 0) LDB_(0, 0)
    LDA_(1, 1) LDB_(1, 1)
    STA_(0, 0) STB_(0, 0)
    __syncthreads();
    for (int i = 0; i < NC; i++) {
        mma_chunk(Ab[i & 1], Bf[i & 1], wm, wn, lane, acc);
        if (i + 2 < NC) { LDA_(i & 1, i + 2) LDB_(i & 1, i + 2) }
        if (i + 1 < NC) {
            STA_((i + 1) & 1, (i + 1) & 1) STB_((i + 1) & 1, (i + 1) & 1)
            __syncthreads();
        }
    }
    __syncthreads();
    #undef LDA_
    #undef LDB_
    #undef STA_
    #undef STB_
    epilogue(acc, bias, C, ldc, bn, Nc, act, kPl, kpsz, wm, wn, lane);
}

// ---------------- memupd tile (cvt, single-buffer) + pMem emit ---------------
static __device__ void tile_memupd(int tn, int tm, u32* shb)
{
    const int lane = threadIdx.x & 31, wid = threadIdx.x >> 5;
    const int wm = wid & 3, wn = wid >> 2;
    const int bnrow = tn * 64, bmcol = tm * 64;
    u32* Wb = shb;
    u32* Eb = shb + 2560;
    u32* Ab = shb + 5120;
    float acce[4][4] = {};
    float acca[4][4] = {};

    {
        StT sw = load_T(g_ww, Nn, bnrow, 1 << 30, 0);
        StT se = load_T(g_ea, 2 * Mm, bmcol, 1 << 30, 0);
        StT sv = load_T(g_ea, 2 * Mm, Mm + bmcol, 1 << 30, 0);
        store_T(sw, Wb); store_T(se, Eb); store_T(sv, Ab);
    }
    __syncthreads();
    for (int k0 = 0; k0 < Bb; k0 += 16) {
        StT sw, se, sv;
        bool more = (k0 + 16 < Bb);
        if (more) {
            sw = load_T(g_ww, Nn, bnrow, 1 << 30, k0 + 16);
            se = load_T(g_ea, 2 * Mm, bmcol, 1 << 30, k0 + 16);
            sv = load_T(g_ea, 2 * Mm, Mm + bmcol, 1 << 30, k0 + 16);
        }
        {
            int r = lane >> 2, w = lane & 3;
            const u32* Ah = Wb + (wm * 16 + r) * 20 + w;
            u32 a0 = Ah[0], a1 = Ah[160], a2 = Ah[4], a3 = Ah[164];
            u32 e0 = Ah[1280], e1 = Ah[1440], e2 = Ah[1284], e3 = Ah[1444];
            #pragma unroll
            for (int j = 0; j < 4; j++) {
                const u32* Bh = Eb + (wn * 32 + j * 8 + r) * 20 + w;
                u32 b0 = Bh[0], b1 = Bh[4], f0 = Bh[1280], f1 = Bh[1284];
                mma16816(acce[j], a0, a1, a2, a3, b0, b1);
                mma16816(acce[j], a0, a1, a2, a3, f0, f1);
                mma16816(acce[j], e0, e1, e2, e3, b0, b1);
                const u32* Ch = Ab + (wn * 32 + j * 8 + r) * 20 + w;
                u32 g0 = Ch[0], g1 = Ch[4], h0 = Ch[1280], h1 = Ch[1284];
                mma16816(acca[j], a0, a1, a2, a3, g0, g1);
                mma16816(acca[j], a0, a1, a2, a3, h0, h1);
                mma16816(acca[j], e0, e1, e2, e3, g0, g1);
            }
        }
        __syncthreads();
        if (more) {
            store_T(sw, Wb); store_T(se, Eb); store_T(sv, Ab);
        }
        __syncthreads();
    }
    const float invB = 1.f / (float)Bb;
    int r = lane >> 2, c2 = (lane & 3) * 2;
    #pragma unroll
    for (int j = 0; j < 4; j++) {
        int m0 = bmcol + wn * 32 + j * 8 + c2;
        #pragma unroll
        for (int rr = 0; rr < 2; rr++) {
            int n = bnrow + wm * 16 + r + rr * 8;
            float e0v = acce[j][rr * 2 + 0], e1v = acce[j][rr * 2 + 1];
            float a0v = acca[j][rr * 2 + 0], a1v = acca[j][rr * 2 + 1];
            float o0 = g_mem[(size_t)n * Mm + m0];
            float o1 = g_mem[(size_t)n * Mm + m0 + 1];
            float nv0 = o0 * (1.f - e0v * invB) + a0v * invB;
            float nv1 = o1 * (1.f - e1v * invB) + a1v * invB;
            g_mem[(size_t)n * Mm + m0] = nv0;
            g_mem[(size_t)n * Mm + m0 + 1] = nv1;
            u32 hi, lo;
            split2(nv0, nv1, hi, lo);
            pMem[(size_t)n * 256 + (m0 >> 1)] = hi;
            pMem[PSZ_MEM + (size_t)n * 256 + (m0 >> 1)] = lo;
        }
    }
}

// ---------------- small row-wise items ----------------------------------------
static __device__ __noinline__ void invnorm_item(int item)
{
    int w = threadIdx.x >> 5, lane = threadIdx.x & 31;
    for (int rr = w; rr < 128; rr += 8) {
        int n = item * 128 + rr;
        float s = 0.f;
        for (int c = lane; c < Mm; c += 32) {
            float v = g_mem[(size_t)n * Mm + c];
            s += v * v;
        }
        s = warpReduceSum(s);
        if (lane == 0) g_invmem[n] = 1.f / (sqrtf(s) + 1e-8f);
    }
}
static __device__ __noinline__ void scalars_item(int i)
{
    int head = i >> 3, rb = i & 7;
    const float* p = head ? g_pr : g_pw;
    float* sc = head ? g_scr : g_scw;
    int w = threadIdx.x >> 5, lane = threadIdx.x & 31;
    for (int rr = w; rr < 32; rr += 8) {
        int b = rb * 32 + rr;
        const float* row = p + (size_t)b * (Mm + 6);
        float s = 0.f;
        for (int c = lane; c < Mm; c += 32) {
            float v = row[c];
            s += v * v;
        }
        s = warpReduceSum(s);
        if (lane == 0) {
            sc[b * 8 + 0] = softplus_(row[Mm + 0]);
            sc[b * 8 + 1] = sigm(row[Mm + 1]);
            float s0 = row[Mm + 2], s1 = row[Mm + 3], s2 = row[Mm + 4];
            float mx = fmaxf(s0, fmaxf(s1, s2));
            float e0 = __expf(s0 - mx), e1 = __expf(s1 - mx), e2 = __expf(s2 - mx);
            float inv = 1.f / (e0 + e1 + e2);
            sc[b * 8 + 2] = e0 * inv;
            sc[b * 8 + 3] = e1 * inv;
            sc[b * 8 + 4] = e2 * inv;
            sc[b * 8 + 5] = 1.f + softplus_(row[Mm + 5]);
            sc[b * 8 + 6] = 1.f / (sqrtf(s) + 1e-8f);
        }
    }
}

// -------- fused address tail; head==1 (wr) also emits wrP planes --------------
static __device__ __noinline__ void tail_item(int it, float* shb)
{
    float* wg = shb;
    int b = it & 255, head = it >> 8;
    const float* sim = head ? g_simr : g_simw;
    float* wv = head ? g_wr : g_ww;
    const float* sc = head ? g_scr : g_scw;
    int tid = threadIdx.x;
    int nb = tid * 4;
    float beta = sc[b * 8 + 0], g = sc[b * 8 + 1];
    float s0 = sc[b * 8 + 2], s1 = sc[b * 8 + 3], s2 = sc[b * 8 + 4];
    float gamma = sc[b * 8 + 5], invk = sc[b * 8 + 6];
    float scale = beta * invk;

    float4 sv = *(const float4*)&sim[(size_t)b * Nn + nb];
    float4 iv = *(const float4*)&g_invmem[nb];
    float v[4] = {sv.x * scale * iv.x, sv.y * scale * iv.y,
                  sv.z * scale * iv.z, sv.w * scale * iv.w};
    float mx = fmaxf(fmaxf(v[0], v[1]), fmaxf(v[2], v[3]));
    mx = blockReduceMax256(mx);
    float s = 0.f;
    #pragma unroll
    for (int i = 0; i < 4; i++) { v[i] = __expf(v[i] - mx); s += v[i]; }
    s = blockReduceSum256(s);
    float invs = 1.f / s;
    float4 wp4 = *(const float4*)&wv[(size_t)b * Nn + nb];
    float wpv[4] = {wp4.x, wp4.y, wp4.z, wp4.w};
    #pragma unroll
    for (int i = 0; i < 4; i++)
        wg[nb + i] = g * (v[i] * invs) + (1.f - g) * wpv[i];
    __syncthreads();
    float o[4];
    float local = 0.f;
    #pragma unroll
    for (int i = 0; i < 4; i++) {
        int n = nb + i;
        float wt = s0 * wg[(n + 1) & (Nn - 1)] + s1 * wg[n] + s2 * wg[(n - 1) & (Nn - 1)];
        float pv = __powf(wt, gamma);
        o[i] = pv;
        local += pv;
    }
    local = blockReduceSum256(local);
    float invt = 1.f / (local + 1e-8f);
    #pragma unroll
    for (int i = 0; i < 4; i++) o[i] *= invt;
    *(float4*)&wv[(size_t)b * Nn + nb] = make_float4(o[0], o[1], o[2], o[3]);
    if (head) {
        u32 h0, l0, h1, l1;
        split2(o[0], o[1], h0, l0);
        split2(o[2], o[3], h1, l1);
        size_t kw = (size_t)b * 512 + (nb >> 1);
        pWrp[kw] = h0; pWrp[kw + 1] = h1;
        pWrp[PSZ_WR + kw] = l0; pWrp[PSZ_WR + kw + 1] = l1;
    }
    __syncthreads();
}

// ---------------- P0 converters -----------------------------------------------
static __device__ void conv_T(u32* dst, const float* __restrict__ src,
                              int R, int VR, int ldw, int gtid, int gstride)
{
    size_t psz = (size_t)R * 256;
    for (size_t idx = gtid; idx < psz; idx += gstride) {
        int kw = (int)(idx / R);
        int row = (int)(idx - (size_t)kw * R);
        float v0 = 0.f, v1 = 0.f;
        if (row < VR) {
            v0 = src[(size_t)(2 * kw) * ldw + row];
            v1 = src[(size_t)(2 * kw + 1) * ldw + row];
        }
        u32 hi, lo;
        split2(v0, v1, hi, lo);
        dst[(size_t)row * 256 + kw] = hi;
        dst[psz + (size_t)row * 256 + kw] = lo;
    }
}
static __device__ void conv_P(u32* dst, const float* __restrict__ src,
                              size_t npairs, size_t psz, int gtid, int gstride)
{
    for (size_t i = gtid; i < npairs; i += gstride) {
        float2 v = *(const float2*)(src + 2 * i);
        u32 hi, lo;
        split2(v.x, v.y, hi, lo);
        dst[i] = hi;
        dst[psz + i] = lo;
    }
}

// ---------------- the persistent kernel ---------------------------------------
__global__ void __launch_bounds__(NTHR, 1) ntm_persistent(
    const float* __restrict__ x,
    const float* __restrict__ mem0, const float* __restrict__ wr0,
    const float* __restrict__ ww0,  const float* __restrict__ h0,
    const float* __restrict__ Wx,   const float* __restrict__ Wr,
    const float* __restrict__ bh,
    const float* __restrict__ Whr,  const float* __restrict__ bhr,
    const float* __restrict__ Whw,  const float* __restrict__ bhw,
    const float* __restrict__ Wea,  const float* __restrict__ bea,
    const float* __restrict__ Wo,   const float* __restrict__ bo,
    float* __restrict__ out)
{
    extern __shared__ __align__(16) u32 shb[];   // 80 KB dynamic
    const int tid = threadIdx.x;
    const int gtid = blockIdx.x * NTHR + tid;
    const int gstride = NBLK * NTHR;

    // P0
    for (int i = gtid; i < Nn * Mm; i += gstride) g_mem[i] = mem0[i];
    for (int i = gtid; i < Bb * Nn; i += gstride) { g_wr[i] = wr0[i]; g_ww[i] = ww0[i]; }
    for (int i = gtid; i < Bb * Hh; i += gstride) g_h[i] = h0[i];
    conv_P(pH, h0, PSZ_H, PSZ_H, gtid, gstride);
    conv_P(pWrp, wr0, PSZ_WR, PSZ_WR, gtid, gstride);
    conv_P(pX, x, PSZ_X, PSZ_X, gtid, gstride);
    conv_T(pWxT, Wx, 512, 512, Hh, gtid, gstride);
    conv_T(pWrT, Wr, 512, 512, Hh, gtid, gstride);
    conv_T(pWoT, Wo, 512, 512, Oo, gtid, gstride);
    conv_T(pWhwT, Whw, 576, Mm + 6, Mm + 6, gtid, gstride);
    conv_T(pWhrT, Whr, 576, Mm + 6, Mm + 6, gtid, gstride);
    conv_T(pWeaT, Wea, 1024, 1024, 2 * Mm, gtid, gstride);
    gridBarrier();

    // P1: ea from h0
    for (int it = blockIdx.x; it < 64; it += NBLK) {
        int tm = it >> 4, tn = it & 15;
        tile_pp(pH + (size_t)tm * 64 * 256, 256, PSZ_H,
                pWeaT + (size_t)tn * 64 * 256, 256, PSZ_WEA,
                bea, g_ea + (size_t)tm * 64 * (2 * Mm), 2 * Mm,
                tn * 64, 2 * Mm, Hh, 4, 0, 0, shb);
    }
    gridBarrier();

    for (int t = 0; t < Tt; t++) {
        // B: memupd (128) + out_{t-1} tiles 0..19
        for (int it = blockIdx.x; it < 148; it += NBLK) {
            if (it < 128) tile_memupd(it >> 3, it & 7, shb);
            else if (t > 0) {
                int o = it - 128, tm = o >> 3, tn = o & 7;
                tile_pp(pH + (size_t)tm * 64 * 256, 256, PSZ_H,
                        pWoT + (size_t)tn * 64 * 256, 256, PSZ_WT,
                        bo, out + (size_t)(t - 1) * Oo + (size_t)tm * 64 * Tt * Oo,
                        (size_t)Tt * Oo, tn * 64, Oo, Hh, 2, 0, 0, shb);
            }
        }
        gridBarrier();

        // C: r split-K (128) + invnorm (8) + out_{t-1} tiles 20..31
        for (int it = blockIdx.x; it < 148; it += NBLK) {
            if (it < 128) {
                int c = it >> 5, rest = it & 31, tm = rest >> 3, tn = rest & 7;
                tile_gemm(pWrp + (size_t)tm * 64 * 512 + c * 128, 512, PSZ_WR, 0, 0, 0,
                          0, 0, 0, g_mem + (size_t)c * 256 * Mm + tn * 64, Mm,
                          nullptr, g_rpart + (size_t)c * BM + (size_t)tm * 64 * Mm, Mm,
                          tn * 64, 1 << 30, 256, 0, 0, 0, shb);
            } else if (it < 136) invnorm_item(it - 128);
            else if (t > 0) {
                int o = it - 136 + 20, tm = o >> 3, tn = o & 7;
                tile_pp(pH + (size_t)tm * 64 * 256, 256, PSZ_H,
                        pWoT + (size_t)tn * 64 * 256, 256, PSZ_WT,
                        bo, out + (size_t)(t - 1) * Oo + (size_t)tm * 64 * Tt * Oo,
                        (size_t)Tt * Oo, tn * 64, Oo, Hh, 2, 0, 0, shb);
            }
        }
        gridBarrier();

        // D: controller split-K (128)
        for (int it = blockIdx.x; it < 128; it += NBLK) {
            int c = it >> 5, rest = it & 31, tm = rest >> 3, tn = rest & 7;
            if (c < 2) {
                tile_pp(pX + (size_t)tm * 64 * 32768 + (size_t)t * 256 + c * 128,
                        32768, PSZ_X,
                        pWxT + (size_t)tn * 64 * 256 + c * 128, 256, PSZ_WT,
                        nullptr, g_hpart + (size_t)c * BH + (size_t)tm * 64 * Hh, Hh,
                        tn * 64, 1 << 30, 256, 0, 0, 0, shb);
            } else {
                tile_gemm(0, 0, 0, g_rpart + (size_t)tm * 64 * Mm + (c - 2) * 256, Mm, BM,
                          pWrT + (size_t)tn * 64 * 256 + (c - 2) * 128, 256, PSZ_WT, 0, 0,
                          nullptr, g_hpart + (size_t)c * BH + (size_t)tm * 64 * Hh, Hh,
                          tn * 64, 1 << 30, 256, 0, 0, 0, shb);
            }
        }
        gridBarrier();

        // D2
        for (int i = gtid; i < BH / 2; i += gstride) {
            int i2 = 2 * i;
            float a0 = g_hpart[i2] + g_hpart[i2 + BH] + g_hpart[i2 + 2 * BH]
                       + g_hpart[i2 + 3 * BH] + bh[i2 & 511];
            float a1 = g_hpart[i2 + 1] + g_hpart[i2 + 1 + BH] + g_hpart[i2 + 1 + 2 * BH]
                       + g_hpart[i2 + 1 + 3 * BH] + bh[(i2 + 1) & 511];
            float v0 = tanh_f(a0), v1 = tanh_f(a1);
            g_h[i2] = v0; g_h[i2 + 1] = v1;
            u32 hi, lo;
            split2(v0, v1, hi, lo);
            pH[i] = hi; pH[PSZ_H + i] = lo;
        }
        gridBarrier();

        // E: pw(36) + pr(36) + ea-next(64)
        for (int it = blockIdx.x; it < 136; it += NBLK) {
            if (it < 72) {
                int head = it >= 36, i2 = head ? it - 36 : it;
                int tm = i2 / 9, tn = i2 % 9;
                const u32* WT = head ? pWhrT : pWhwT;
                const float* bb = head ? bhr : bhw;
                float* P = head ? g_pr : g_pw;
                u32* kP = head ? pKr : pKw;
                tile_pp(pH + (size_t)tm * 64 * 256, 256, PSZ_H,
                        WT + (size_t)tn * 64 * 256, 256, PSZ_WH,
                        bb, P + (size_t)tm * 64 * (Mm + 6), Mm + 6,
                        tn * 64, Mm + 6, Hh, 3,
                        kP + (size_t)tm * 64 * 256, PSZ_K, shb);
            } else {
                int i2 = it - 72, tm = i2 >> 4, tn = i2 & 15;
                tile_pp(pH + (size_t)tm * 64 * 256, 256, PSZ_H,
                        pWeaT + (size_t)tn * 64 * 256, 256, PSZ_WEA,
                        bea, g_ea + (size_t)tm * 64 * (2 * Mm), 2 * Mm,
                        tn * 64, 2 * Mm, Hh, 4, 0, 0, shb);
            }
        }
        gridBarrier();

        // F: simw(64) simr(64) + head scalars(16)
        for (int it = blockIdx.x; it < 144; it += NBLK) {
            if (it < 128) {
                int head = it >= 64, i2 = head ? it - 64 : it;
                int tm = i2 >> 4, tn = i2 & 15;
                const u32* kP = head ? pKr : pKw;
                float* S = head ? g_simr : g_simw;
                tile_pp(kP + (size_t)tm * 64 * 256, 256, PSZ_K,
                        pMem + (size_t)tn * 64 * 256, 256, PSZ_MEM,
                        nullptr, S + (size_t)tm * 64 * Nn, Nn,
                        tn * 64, 1 << 30, Mm, 0, 0, 0, shb);
            } else scalars_item(it - 128);
        }
        gridBarrier();

        // G: address tails
        for (int it = blockIdx.x; it < 512; it += NBLK)
            tail_item(it, (float*)shb);
        gridBarrier();
    }

    for (int it = blockIdx.x; it < 32; it += NBLK) {
        int tm = it >> 3, tn = it & 7;
        tile_pp(pH + (size_t)tm * 64 * 256, 256, PSZ_H,
                pWoT + (size_t)tn * 64 * 256, 256, PSZ_WT,
                bo, out + (size_t)(Tt - 1) * Oo + (size_t)tm * 64 * Tt * Oo,
                (size_t)Tt * Oo, tn * 64, Oo, Hh, 2, 0, 0, shb);
    }
}

// ---------------- host --------------------------------------------------------
extern "C" void kernel_launch(void* const* d_in, const int* in_sizes, int n_in,
                              void* d_out, int out_size)
{
    const float* x    = (const float*)d_in[0];
    const float* mem0 = (const float*)d_in[1];
    const float* wr0  = (const float*)d_in[2];
    const float* ww0  = (const float*)d_in[3];
    const float* h0   = (const float*)d_in[4];
    const float* Wx   = (const float*)d_in[5];
    const float* Wr   = (const float*)d_in[6];
    const float* bh   = (const float*)d_in[7];
    const float* Whr  = (const float*)d_in[8];
    const float* bhr  = (const float*)d_in[9];
    const float* Whw  = (const float*)d_in[10];
    const float* bhw  = (const float*)d_in[11];
    const float* Wea  = (const float*)d_in[12];
    const float* bea  = (const float*)d_in[13];
    const float* Wo   = (const float*)d_in[14];
    const float* bo   = (const float*)d_in[15];
    float* out = (float*)d_out;

    cudaFuncSetAttribute(ntm_persistent,
                         cudaFuncAttributeMaxDynamicSharedMemorySize, 81920);
    ntm_persistent<<<NBLK, NTHR, 81920>>>(x, mem0, wr0, ww0, h0, Wx, Wr, bh,
                                          Whr, bhr, Whw, bhw, Wea, bea, Wo, bo, out);
}

// round 12
// speedup vs baseline: 1.6478x; 1.0533x over previous
#include <cuda_runtime.h>
#include <math.h>

#define Bb 256
#define Tt 128
#define Ii 512
#define Hh 512
#define Nn 1024
#define Mm 512
#define Oo 512
#define NBLK 148
#define NTHR 256
#define BH (Bb * Hh)
#define BM (Bb * Mm)

typedef unsigned int u32;

#define PSZ_WT 131072u
#define PSZ_WH 147456u
#define PSZ_WEA 262144u
#define PSZ_H 65536u
#define PSZ_K 65536u
#define PSZ_WR 131072u
#define PSZ_MEM 262144u
#define PSZ_X 8388608u

__device__ float g_mem[Nn * Mm];
__device__ float g_wr[Bb * Nn];
__device__ float g_ww[Bb * Nn];
__device__ float g_h[Bb * Hh];
__device__ float g_ea[Bb * 2 * Mm];
__device__ float g_rpart[4 * Bb * Mm];
__device__ float g_hpart[4 * Bb * Hh];
__device__ float g_pw[Bb * (Mm + 6)];
__device__ float g_pr[Bb * (Mm + 6)];
__device__ float g_scw[Bb * 8];
__device__ float g_scr[Bb * 8];
__device__ float g_simw[Bb * Nn];
__device__ float g_simr[Bb * Nn];
__device__ float g_invmem[Nn];
__device__ unsigned g_bar_count;
__device__ unsigned g_bar_gen;

__device__ __align__(16) u32 pWxT[2 * PSZ_WT];
__device__ __align__(16) u32 pWrT[2 * PSZ_WT];
__device__ __align__(16) u32 pWoT[2 * PSZ_WT];
__device__ __align__(16) u32 pWhwT[2 * PSZ_WH];
__device__ __align__(16) u32 pWhrT[2 * PSZ_WH];
__device__ __align__(16) u32 pWeaT[2 * PSZ_WEA];
__device__ __align__(16) u32 pH[2 * PSZ_H];
__device__ __align__(16) u32 pKw[2 * PSZ_K];
__device__ __align__(16) u32 pKr[2 * PSZ_K];
__device__ __align__(16) u32 pWrp[2 * PSZ_WR];
__device__ __align__(16) u32 pMem[2 * PSZ_MEM];
__device__ __align__(16) u32 pX[2 * PSZ_X];

static __device__ __forceinline__ void gridBarrier() {
    __syncthreads();
    __threadfence();
    if (threadIdx.x == 0) {
        unsigned gen = *(volatile unsigned*)&g_bar_gen;
        unsigned prev = atomicAdd(&g_bar_count, 1u);
        if (prev == NBLK - 1) {
            g_bar_count = 0;
            __threadfence();
            *(volatile unsigned*)&g_bar_gen = gen + 1;
        } else {
            while (*(volatile unsigned*)&g_bar_gen == gen) {}
        }
    }
    __syncthreads();
}

// ---------------- math helpers ----------------------------------------------
static __device__ __forceinline__ float sigm(float x) { return 1.f / (1.f + __expf(-x)); }
static __device__ __forceinline__ float tanh_f(float x) {
    float t = __expf(-2.f * fabsf(x));
    float r = (1.f - t) / (1.f + t);
    return copysignf(r, x);
}
static __device__ __forceinline__ float softplus_(float x) {
    return fmaxf(x, 0.f) + log1pf(__expf(-fabsf(x)));
}
static __device__ __forceinline__ float warpReduceSum(float v) {
    #pragma unroll
    for (int o = 16; o > 0; o >>= 1) v += __shfl_xor_sync(0xffffffffu, v, o);
    return v;
}
static __device__ __forceinline__ float warpReduceMax(float v) {
    #pragma unroll
    for (int o = 16; o > 0; o >>= 1) v = fmaxf(v, __shfl_xor_sync(0xffffffffu, v, o));
    return v;
}
static __device__ __forceinline__ float warpReduceSum32(float v) { return warpReduceSum(v); }

// ---------------- bf16 split + mma -------------------------------------------
static __device__ __forceinline__ void split2(float x0, float x1, u32 &hi, u32 &lo) {
    u32 h;
    asm("cvt.rn.bf16x2.f32 %0, %1, %2;" : "=r"(h) : "f"(x1), "f"(x0));
    float h0 = __uint_as_float(h << 16);
    float h1 = __uint_as_float(h & 0xffff0000u);
    asm("cvt.rn.bf16x2.f32 %0, %1, %2;" : "=r"(lo) : "f"(x1 - h1), "f"(x0 - h0));
    hi = h;
}
static __device__ __forceinline__ void mma16816(float* c,
    u32 a0, u32 a1, u32 a2, u32 a3, u32 b0, u32 b1)
{
    asm("mma.sync.aligned.m16n8k16.row.col.f32.bf16.bf16.f32 "
        "{%0,%1,%2,%3},{%4,%5,%6,%7},{%8,%9},{%0,%1,%2,%3};"
        : "+f"(c[0]), "+f"(c[1]), "+f"(c[2]), "+f"(c[3])
        : "r"(a0), "r"(a1), "r"(a2), "r"(a3), "r"(b0), "r"(b1));
}
static __device__ __forceinline__ void cpa16(u32* s, const u32* g) {
    unsigned sa = (unsigned)__cvta_generic_to_shared(s);
    asm volatile("cp.async.ca.shared.global [%0], [%1], 16;" :: "r"(sa), "l"(g));
}

// ---------------- cvt staging (for memupd / mem-T / rpart-sum) ----------------
struct StR { float2 v[2]; };
static __device__ __forceinline__ StR load_rows(const float* __restrict__ A,
    size_t lda, int k0, int nsum, size_t sstr)
{
    int t = threadIdx.x;
    int row = t >> 2, w = t & 3;
    const float* p = A + (size_t)row * lda + k0 + 2 * w;
    StR s;
    #pragma unroll
    for (int i = 0; i < 2; i++) {
        float2 v = *(const float2*)(p + 8 * i);
        if (nsum == 4) {
            #pragma unroll
            for (int q = 1; q < 4; q++) {
                float2 u = *(const float2*)(p + 8 * i + q * sstr);
                v.x += u.x; v.y += u.y;
            }
        }
        s.v[i] = v;
    }
    return s;
}
static __device__ __forceinline__ void store_rows(StR s, u32* sm) {
    int t = threadIdx.x;
    int row = t >> 2, w = t & 3;
    #pragma unroll
    for (int i = 0; i < 2; i++) {
        u32 hi, lo;
        split2(s.v[i].x, s.v[i].y, hi, lo);
        sm[row * 20 + w + 4 * i] = hi;
        sm[1280 + row * 20 + w + 4 * i] = lo;
    }
}
struct StT { float v[4]; };
static __device__ __forceinline__ StT load_T(const float* __restrict__ W,
    size_t ldw, int cb, int Nc, int k0)
{
    int t = threadIdx.x;
    int p = t >> 5, n0 = t & 31;
    const float* r0 = W + (size_t)(k0 + 2 * p) * ldw + cb;
    StT s;
    #pragma unroll
    for (int i = 0; i < 2; i++) {
        int n = n0 + 32 * i;
        float v0 = 0.f, v1 = 0.f;
        if (cb + n < Nc) { v0 = r0[n]; v1 = r0[ldw + n]; }
        s.v[2 * i] = v0; s.v[2 * i + 1] = v1;
    }
    return s;
}
static __device__ __forceinline__ void store_T(StT s, u32* sm) {
    int t = threadIdx.x;
    int p = t >> 5, n0 = t & 31;
    #pragma unroll
    for (int i = 0; i < 2; i++) {
        int n = n0 + 32 * i;
        u32 hi, lo;
        split2(s.v[2 * i], s.v[2 * i + 1], hi, lo);
        sm[n * 20 + p] = hi;
        sm[1280 + n * 20 + p] = lo;
    }
}

// ---------------- warp compute for one k16 chunk ------------------------------
static __device__ __forceinline__ void mma_chunk(const u32* As, const u32* Bs,
    int wm, int wn, int lane, float acc[4][4])
{
    int r = lane >> 2, w = lane & 3;
    const u32* Ah = As + (wm * 16 + r) * 20 + w;
    u32 a0 = Ah[0], a1 = Ah[160], a2 = Ah[4], a3 = Ah[164];
    u32 e0 = Ah[1280], e1 = Ah[1440], e2 = Ah[1284], e3 = Ah[1444];
    #pragma unroll
    for (int j = 0; j < 4; j++) {
        const u32* Bh = Bs + (wn * 32 + j * 8 + r) * 20 + w;
        u32 b0 = Bh[0], b1 = Bh[4];
        u32 f0 = Bh[1280], f1 = Bh[1284];
        mma16816(acc[j], a0, a1, a2, a3, b0, b1);
        mma16816(acc[j], a0, a1, a2, a3, f0, f1);
        mma16816(acc[j], e0, e1, e2, e3, b0, b1);
    }
}

// ---------------- shared epilogue --------------------------------------------
static __device__ __forceinline__ void epilogue(float acc[4][4],
    const float* bias, float* C, size_t ldc, int bn, int Nc, int act,
    u32* kPl, size_t kpsz, int wm, int wn, int lane)
{
    int r = lane >> 2, c2 = (lane & 3) * 2;
    #pragma unroll
    for (int j = 0; j < 4; j++) {
        int col0 = bn + wn * 32 + j * 8 + c2;
        #pragma unroll
        for (int rr = 0; rr < 2; rr++) {
            int row = wm * 16 + r + rr * 8;
            float v0 = acc[j][rr * 2 + 0], v1 = acc[j][rr * 2 + 1];
            bool ok0 = col0 < Nc, ok1 = (col0 + 1) < Nc;
            if (bias) { if (ok0) v0 += bias[col0]; if (ok1) v1 += bias[col0 + 1]; }
            if (act == 2) { v0 = sigm(v0); v1 = sigm(v1); }
            else if (act == 3) { if (col0 < 512) { v0 = tanh_f(v0); v1 = tanh_f(v1); } }
            else if (act == 4) {
                if (col0 < 512) { v0 = sigm(v0); v1 = sigm(v1); }
                else { v0 = tanh_f(v0); v1 = tanh_f(v1); }
            }
            if (ok0) C[(size_t)row * ldc + col0] = v0;
            if (ok1) C[(size_t)row * ldc + col0 + 1] = v1;
            if (kPl && col0 < 512) {
                u32 hi, lo;
                split2(v0, v1, hi, lo);
                kPl[(size_t)row * 256 + (col0 >> 1)] = hi;
                kPl[kpsz + (size_t)row * 256 + (col0 >> 1)] = lo;
            }
        }
    }
}

// ------ plane-plane tile: cp.async, 6 buffers, 2 chunks per sync --------------
static __device__ void tile_pp(
    const u32* aPl, size_t arw, size_t apsz,
    const u32* bPl, size_t brw, size_t bpsz,
    const float* bias, float* C, size_t ldc,
    int bn, int Nc, int K, int act,
    u32* kPl, size_t kpsz, u32* shb)
{
    const int lane = threadIdx.x & 31, wid = threadIdx.x >> 5;
    const int wm = wid & 3, wn = wid >> 2;
    const int t = threadIdx.x;
    const int row = t >> 2, hf = (t >> 1) & 1, pl = t & 1;
    const u32* ga = aPl + (size_t)pl * apsz + (size_t)row * arw + hf * 4;
    const u32* gb = bPl + (size_t)pl * bpsz + (size_t)row * brw + hf * 4;
    const int soff = pl * 1280 + row * 20 + hf * 4;
    float acc[4][4] = {};
    const int NC = K >> 4;

    #define ISS(ci) { u32* bb_ = shb + ((ci) % 6) * 5120;                       \
                      cpa16(bb_ + soff, ga + (size_t)(ci) * 8);                 \
                      cpa16(bb_ + 2560 + soff, gb + (size_t)(ci) * 8);          \
                      asm volatile("cp.async.commit_group;"); }
    ISS(0) ISS(1) ISS(2) ISS(3)
    for (int i = 0; i < NC; i += 2) {
        asm volatile("cp.async.wait_group 2;");
        __syncthreads();
        if (i + 4 < NC) ISS(i + 4)
        if (i + 5 < NC) ISS(i + 5)
        const u32* b0 = shb + (i % 6) * 5120;
        const u32* b1 = shb + ((i + 1) % 6) * 5120;
        mma_chunk(b0, b0 + 2560, wm, wn, lane, acc);
        mma_chunk(b1, b1 + 2560, wm, wn, lane, acc);
    }
    asm volatile("cp.async.wait_group 0;");
    __syncthreads();
    #undef ISS
    epilogue(acc, bias, C, ldc, bn, Nc, act, kPl, kpsz, wm, wn, lane);
}

// ---------------- mixed tile (A plane or cvt-sum, B plane or cvt-T) ----------
static __device__ void tile_gemm(
    const u32* aPl, size_t arw, size_t apsz,
    const float* aF, size_t lda, size_t sstr,
    const u32* bPl, size_t brw, size_t bpsz,
    const float* bF, size_t ldb,
    const float* bias, float* C, size_t ldc,
    int bn, int Nc, int K, int act,
    u32* kPl, size_t kpsz, u32* shb)
{
    const int lane = threadIdx.x & 31, wid = threadIdx.x >> 5;
    const int wm = wid & 3, wn = wid >> 2;
    const int t = threadIdx.x;
    const int crow = t >> 2, cg = (t & 3) * 2;
    float acc[4][4] = {};
    u32* Ab[2] = {shb, shb + 2560};
    u32* Bf[2] = {shb + 5120, shb + 7680};
    const u32* aH = aPl ? aPl + (size_t)crow * arw + cg : (const u32*)0;
    const u32* bH = bPl ? bPl + (size_t)crow * brw + cg : (const u32*)0;

    uint2 rA[2][2], rB[2][2];
    StR sA[2]; StT sB[2];
    const int NC = K >> 4;

    #define LDA_(s, ci) { if (aPl) { rA[s][0] = *(const uint2*)(aH + (size_t)(ci) * 8); \
                                     rA[s][1] = *(const uint2*)(aH + apsz + (size_t)(ci) * 8); } \
                          else sA[s] = load_rows(aF, lda, (ci) * 16, 4, sstr); }
    #define LDB_(s, ci) { if (bPl) { rB[s][0] = *(const uint2*)(bH + (size_t)(ci) * 8); \
                                     rB[s][1] = *(const uint2*)(bH + bpsz + (size_t)(ci) * 8); } \
                          else sB[s] = load_T(bF, ldb, 0, 1 << 30, (ci) * 16); }
    #define STA_(s, b) { if (aPl) { *(uint2*)(Ab[b] + crow * 20 + cg) = rA[s][0]; \
                                    *(uint2*)(Ab[b] + 1280 + crow * 20 + cg) = rA[s][1]; } \
                         else store_rows(sA[s], Ab[b]); }
    #define STB_(s, b) { if (bPl) { *(uint2*)(Bf[b] + crow * 20 + cg) = rB[s][0]; \
                                    *(uint2*)(Bf[b] + 1280 + crow * 20 + cg) = rB[s][1]; } \
                         else store_T(sB[s], Bf[b]); }

    LDA_(0, 0) LDB_(0, 0)
    LDA_(1, 1) LDB_(1, 1)
    STA_(0, 0) STB_(0, 0)
    __syncthreads();
    for (int i = 0; i < NC; i++) {
        mma_chunk(Ab[i & 1], Bf[i & 1], wm, wn, lane, acc);
        if (i + 2 < NC) { LDA_(i & 1, i + 2) LDB_(i & 1, i + 2) }
        if (i + 1 < NC) {
            STA_((i + 1) & 1, (i + 1) & 1) STB_((i + 1) & 1, (i + 1) & 1)
            __syncthreads();
        }
    }
    __syncthreads();
    #undef LDA_
    #undef LDB_
    #undef STA_
    #undef STB_
    epilogue(acc, bias, C, ldc, bn, Nc, act, kPl, kpsz, wm, wn, lane);
}

// ---------------- memupd tile (cvt, single-buffer) + pMem emit ---------------
static __device__ void tile_memupd(int tn, int tm, u32* shb)
{
    const int lane = threadIdx.x & 31, wid = threadIdx.x >> 5;
    const int wm = wid & 3, wn = wid >> 2;
    const int bnrow = tn * 64, bmcol = tm * 64;
    u32* Wb = shb;
    u32* Eb = shb + 2560;
    u32* Ab = shb + 5120;
    float acce[4][4] = {};
    float acca[4][4] = {};

    {
        StT sw = load_T(g_ww, Nn, bnrow, 1 << 30, 0);
        StT se = load_T(g_ea, 2 * Mm, bmcol, 1 << 30, 0);
        StT sv = load_T(g_ea, 2 * Mm, Mm + bmcol, 1 << 30, 0);
        store_T(sw, Wb); store_T(se, Eb); store_T(sv, Ab);
    }
    __syncthreads();
    for (int k0 = 0; k0 < Bb; k0 += 16) {
        StT sw, se, sv;
        bool more = (k0 + 16 < Bb);
        if (more) {
            sw = load_T(g_ww, Nn, bnrow, 1 << 30, k0 + 16);
            se = load_T(g_ea, 2 * Mm, bmcol, 1 << 30, k0 + 16);
            sv = load_T(g_ea, 2 * Mm, Mm + bmcol, 1 << 30, k0 + 16);
        }
        {
            int r = lane >> 2, w = lane & 3;
            const u32* Ah = Wb + (wm * 16 + r) * 20 + w;
            u32 a0 = Ah[0], a1 = Ah[160], a2 = Ah[4], a3 = Ah[164];
            u32 e0 = Ah[1280], e1 = Ah[1440], e2 = Ah[1284], e3 = Ah[1444];
            #pragma unroll
            for (int j = 0; j < 4; j++) {
                const u32* Bh = Eb + (wn * 32 + j * 8 + r) * 20 + w;
                u32 b0 = Bh[0], b1 = Bh[4], f0 = Bh[1280], f1 = Bh[1284];
                mma16816(acce[j], a0, a1, a2, a3, b0, b1);
                mma16816(acce[j], a0, a1, a2, a3, f0, f1);
                mma16816(acce[j], e0, e1, e2, e3, b0, b1);
                const u32* Ch = Ab + (wn * 32 + j * 8 + r) * 20 + w;
                u32 g0 = Ch[0], g1 = Ch[4], h0 = Ch[1280], h1 = Ch[1284];
                mma16816(acca[j], a0, a1, a2, a3, g0, g1);
                mma16816(acca[j], a0, a1, a2, a3, h0, h1);
                mma16816(acca[j], e0, e1, e2, e3, g0, g1);
            }
        }
        __syncthreads();
        if (more) {
            store_T(sw, Wb); store_T(se, Eb); store_T(sv, Ab);
        }
        __syncthreads();
    }
    const float invB = 1.f / (float)Bb;
    int r = lane >> 2, c2 = (lane & 3) * 2;
    #pragma unroll
    for (int j = 0; j < 4; j++) {
        int m0 = bmcol + wn * 32 + j * 8 + c2;
        #pragma unroll
        for (int rr = 0; rr < 2; rr++) {
            int n = bnrow + wm * 16 + r + rr * 8;
            float e0v = acce[j][rr * 2 + 0], e1v = acce[j][rr * 2 + 1];
            float a0v = acca[j][rr * 2 + 0], a1v = acca[j][rr * 2 + 1];
            float o0 = g_mem[(size_t)n * Mm + m0];
            float o1 = g_mem[(size_t)n * Mm + m0 + 1];
            float nv0 = o0 * (1.f - e0v * invB) + a0v * invB;
            float nv1 = o1 * (1.f - e1v * invB) + a1v * invB;
            g_mem[(size_t)n * Mm + m0] = nv0;
            g_mem[(size_t)n * Mm + m0 + 1] = nv1;
            u32 hi, lo;
            split2(nv0, nv1, hi, lo);
            pMem[(size_t)n * 256 + (m0 >> 1)] = hi;
            pMem[PSZ_MEM + (size_t)n * 256 + (m0 >> 1)] = lo;
        }
    }
}

// ---------------- small row-wise items ----------------------------------------
static __device__ __noinline__ void invnorm_item(int item)
{
    int w = threadIdx.x >> 5, lane = threadIdx.x & 31;
    for (int rr = w; rr < 128; rr += 8) {
        int n = item * 128 + rr;
        float s = 0.f;
        for (int c = lane; c < Mm; c += 32) {
            float v = g_mem[(size_t)n * Mm + c];
            s += v * v;
        }
        s = warpReduceSum(s);
        if (lane == 0) g_invmem[n] = 1.f / (sqrtf(s) + 1e-8f);
    }
}
static __device__ __noinline__ void scalars_item(int i)
{
    int head = i >> 3, rb = i & 7;
    const float* p = head ? g_pr : g_pw;
    float* sc = head ? g_scr : g_scw;
    int w = threadIdx.x >> 5, lane = threadIdx.x & 31;
    for (int rr = w; rr < 32; rr += 8) {
        int b = rb * 32 + rr;
        const float* row = p + (size_t)b * (Mm + 6);
        float s = 0.f;
        for (int c = lane; c < Mm; c += 32) {
            float v = row[c];
            s += v * v;
        }
        s = warpReduceSum(s);
        if (lane == 0) {
            sc[b * 8 + 0] = softplus_(row[Mm + 0]);
            sc[b * 8 + 1] = sigm(row[Mm + 1]);
            float s0 = row[Mm + 2], s1 = row[Mm + 3], s2 = row[Mm + 4];
            float mx = fmaxf(s0, fmaxf(s1, s2));
            float e0 = __expf(s0 - mx), e1 = __expf(s1 - mx), e2 = __expf(s2 - mx);
            float inv = 1.f / (e0 + e1 + e2);
            sc[b * 8 + 2] = e0 * inv;
            sc[b * 8 + 3] = e1 * inv;
            sc[b * 8 + 4] = e2 * inv;
            sc[b * 8 + 5] = 1.f + softplus_(row[Mm + 5]);
            sc[b * 8 + 6] = 1.f / (sqrtf(s) + 1e-8f);
        }
    }
}

// ------ warp-level address tail: one warp per (b, head), no block syncs -------
static __device__ __noinline__ void tail_warp(int blkit, float* wgall)
{
    int lane = threadIdx.x & 31, w = threadIdx.x >> 5;
    int idx = blkit * 8 + w;          // 0..511
    int b = idx & 255, head = idx >> 8;
    const float* sim = head ? g_simr : g_simw;
    float* wv = head ? g_wr : g_ww;
    const float* sc = head ? g_scr : g_scw;
    float* wg = wgall + w * 1024;
    float beta = sc[b * 8 + 0], g = sc[b * 8 + 1];
    float s0 = sc[b * 8 + 2], s1 = sc[b * 8 + 3], s2 = sc[b * 8 + 4];
    float gamma = sc[b * 8 + 5], invk = sc[b * 8 + 6];
    float scale = beta * invk;

    float v[32];
    float mx = -3.4e38f;
    #pragma unroll
    for (int i = 0; i < 32; i++) {
        int n = lane + 32 * i;
        float t = sim[(size_t)b * Nn + n] * scale * g_invmem[n];
        v[i] = t;
        mx = fmaxf(mx, t);
    }
    mx = warpReduceMax(mx);
    float s = 0.f;
    #pragma unroll
    for (int i = 0; i < 32; i++) { v[i] = __expf(v[i] - mx); s += v[i]; }
    s = warpReduceSum(s);
    float invs = 1.f / s;
    #pragma unroll
    for (int i = 0; i < 32; i++) {
        int n = lane + 32 * i;
        wg[n] = g * (v[i] * invs) + (1.f - g) * wv[(size_t)b * Nn + n];
    }
    __syncwarp();
    float local = 0.f;
    #pragma unroll
    for (int i = 0; i < 32; i++) {
        int n = lane + 32 * i;
        float wt = s0 * wg[(n + 1) & 1023] + s1 * wg[n] + s2 * wg[(n - 1) & 1023];
        float pv = __powf(wt, gamma);
        v[i] = pv;
        local += pv;
    }
    local = warpReduceSum(local);
    float invt = 1.f / (local + 1e-8f);
    #pragma unroll
    for (int i = 0; i < 32; i++) {
        int n = lane + 32 * i;
        float o = v[i] * invt;
        wv[(size_t)b * Nn + n] = o;
        float onext = __shfl_down_sync(0xffffffffu, o, 1);
        if (head && !(lane & 1)) {
            u32 hi, lo;
            split2(o, onext, hi, lo);
            pWrp[(size_t)b * 512 + (n >> 1)] = hi;
            pWrp[PSZ_WR + (size_t)b * 512 + (n >> 1)] = lo;
        }
    }
}

// ---------------- P0 converters -----------------------------------------------
static __device__ void conv_T(u32* dst, const float* __restrict__ src,
                              int R, int VR, int ldw, int gtid, int gstride)
{
    size_t psz = (size_t)R * 256;
    for (size_t idx = gtid; idx < psz; idx += gstride) {
        int kw = (int)(idx / R);
        int row = (int)(idx - (size_t)kw * R);
        float v0 = 0.f, v1 = 0.f;
        if (row < VR) {
            v0 = src[(size_t)(2 * kw) * ldw + row];
            v1 = src[(size_t)(2 * kw + 1) * ldw + row];
        }
        u32 hi, lo;
        split2(v0, v1, hi, lo);
        dst[(size_t)row * 256 + kw] = hi;
        dst[psz + (size_t)row * 256 + kw] = lo;
    }
}
static __device__ void conv_P(u32* dst, const float* __restrict__ src,
                              size_t npairs, size_t psz, int gtid, int gstride)
{
    for (size_t i = gtid; i < npairs; i += gstride) {
        float2 v = *(const float2*)(src + 2 * i);
        u32 hi, lo;
        split2(v.x, v.y, hi, lo);
        dst[i] = hi;
        dst[psz + i] = lo;
    }
}

// ---------------- the persistent kernel ---------------------------------------
__global__ void __launch_bounds__(NTHR, 1) ntm_persistent(
    const float* __restrict__ x,
    const float* __restrict__ mem0, const float* __restrict__ wr0,
    const float* __restrict__ ww0,  const float* __restrict__ h0,
    const float* __restrict__ Wx,   const float* __restrict__ Wr,
    const float* __restrict__ bh,
    const float* __restrict__ Whr,  const float* __restrict__ bhr,
    const float* __restrict__ Whw,  const float* __restrict__ bhw,
    const float* __restrict__ Wea,  const float* __restrict__ bea,
    const float* __restrict__ Wo,   const float* __restrict__ bo,
    float* __restrict__ out)
{
    extern __shared__ __align__(16) u32 shb[];   // 120 KB dynamic
    const int tid = threadIdx.x;
    const int gtid = blockIdx.x * NTHR + tid;
    const int gstride = NBLK * NTHR;

    // P0
    for (int i = gtid; i < Nn * Mm; i += gstride) g_mem[i] = mem0[i];
    for (int i = gtid; i < Bb * Nn; i += gstride) { g_wr[i] = wr0[i]; g_ww[i] = ww0[i]; }
    for (int i = gtid; i < Bb * Hh; i += gstride) g_h[i] = h0[i];
    conv_P(pH, h0, PSZ_H, PSZ_H, gtid, gstride);
    conv_P(pWrp, wr0, PSZ_WR, PSZ_WR, gtid, gstride);
    conv_P(pX, x, PSZ_X, PSZ_X, gtid, gstride);
    conv_T(pWxT, Wx, 512, 512, Hh, gtid, gstride);
    conv_T(pWrT, Wr, 512, 512, Hh, gtid, gstride);
    conv_T(pWoT, Wo, 512, 512, Oo, gtid, gstride);
    conv_T(pWhwT, Whw, 576, Mm + 6, Mm + 6, gtid, gstride);
    conv_T(pWhrT, Whr, 576, Mm + 6, Mm + 6, gtid, gstride);
    conv_T(pWeaT, Wea, 1024, 1024, 2 * Mm, gtid, gstride);
    gridBarrier();

    // P1: ea from h0
    for (int it = blockIdx.x; it < 64; it += NBLK) {
        int tm = it >> 4, tn = it & 15;
        tile_pp(pH + (size_t)tm * 64 * 256, 256, PSZ_H,
                pWeaT + (size_t)tn * 64 * 256, 256, PSZ_WEA,
                bea, g_ea + (size_t)tm * 64 * (2 * Mm), 2 * Mm,
                tn * 64, 2 * Mm, Hh, 4, 0, 0, shb);
    }
    gridBarrier();

    for (int t = 0; t < Tt; t++) {
        // B: memupd (128) + out_{t-1} tiles 0..19
        for (int it = blockIdx.x; it < 148; it += NBLK) {
            if (it < 128) tile_memupd(it >> 3, it & 7, shb);
            else if (t > 0) {
                int o = it - 128, tm = o >> 3, tn = o & 7;
                tile_pp(pH + (size_t)tm * 64 * 256, 256, PSZ_H,
                        pWoT + (size_t)tn * 64 * 256, 256, PSZ_WT,
                        bo, out + (size_t)(t - 1) * Oo + (size_t)tm * 64 * Tt * Oo,
                        (size_t)Tt * Oo, tn * 64, Oo, Hh, 2, 0, 0, shb);
            }
        }
        gridBarrier();

        // C: r split-K (128) + invnorm (8) + out_{t-1} tiles 20..31
        for (int it = blockIdx.x; it < 148; it += NBLK) {
            if (it < 128) {
                int c = it >> 5, rest = it & 31, tm = rest >> 3, tn = rest & 7;
                tile_gemm(pWrp + (size_t)tm * 64 * 512 + c * 128, 512, PSZ_WR, 0, 0, 0,
                          0, 0, 0, g_mem + (size_t)c * 256 * Mm + tn * 64, Mm,
                          nullptr, g_rpart + (size_t)c * BM + (size_t)tm * 64 * Mm, Mm,
                          tn * 64, 1 << 30, 256, 0, 0, 0, shb);
            } else if (it < 136) invnorm_item(it - 128);
            else if (t > 0) {
                int o = it - 136 + 20, tm = o >> 3, tn = o & 7;
                tile_pp(pH + (size_t)tm * 64 * 256, 256, PSZ_H,
                        pWoT + (size_t)tn * 64 * 256, 256, PSZ_WT,
                        bo, out + (size_t)(t - 1) * Oo + (size_t)tm * 64 * Tt * Oo,
                        (size_t)Tt * Oo, tn * 64, Oo, Hh, 2, 0, 0, shb);
            }
        }
        gridBarrier();

        // D: controller split-K (128)
        for (int it = blockIdx.x; it < 128; it += NBLK) {
            int c = it >> 5, rest = it & 31, tm = rest >> 3, tn = rest & 7;
            if (c < 2) {
                tile_pp(pX + (size_t)tm * 64 * 32768 + (size_t)t * 256 + c * 128,
                        32768, PSZ_X,
                        pWxT + (size_t)tn * 64 * 256 + c * 128, 256, PSZ_WT,
                        nullptr, g_hpart + (size_t)c * BH + (size_t)tm * 64 * Hh, Hh,
                        tn * 64, 1 << 30, 256, 0, 0, 0, shb);
            } else {
                tile_gemm(0, 0, 0, g_rpart + (size_t)tm * 64 * Mm + (c - 2) * 256, Mm, BM,
                          pWrT + (size_t)tn * 64 * 256 + (c - 2) * 128, 256, PSZ_WT, 0, 0,
                          nullptr, g_hpart + (size_t)c * BH + (size_t)tm * 64 * Hh, Hh,
                          tn * 64, 1 << 30, 256, 0, 0, 0, shb);
            }
        }
        gridBarrier();

        // D2
        for (int i = gtid; i < BH / 2; i += gstride) {
            int i2 = 2 * i;
            float a0 = g_hpart[i2] + g_hpart[i2 + BH] + g_hpart[i2 + 2 * BH]
                       + g_hpart[i2 + 3 * BH] + bh[i2 & 511];
            float a1 = g_hpart[i2 + 1] + g_hpart[i2 + 1 + BH] + g_hpart[i2 + 1 + 2 * BH]
                       + g_hpart[i2 + 1 + 3 * BH] + bh[(i2 + 1) & 511];
            float v0 = tanh_f(a0), v1 = tanh_f(a1);
            g_h[i2] = v0; g_h[i2 + 1] = v1;
            u32 hi, lo;
            split2(v0, v1, hi, lo);
            pH[i] = hi; pH[PSZ_H + i] = lo;
        }
        gridBarrier();

        // E: pw(36) + pr(36) + ea-next(64)
        for (int it = blockIdx.x; it < 136; it += NBLK) {
            if (it < 72) {
                int head = it >= 36, i2 = head ? it - 36 : it;
                int tm = i2 / 9, tn = i2 % 9;
                const u32* WT = head ? pWhrT : pWhwT;
                const float* bb = head ? bhr : bhw;
                float* P = head ? g_pr : g_pw;
                u32* kP = head ? pKr : pKw;
                tile_pp(pH + (size_t)tm * 64 * 256, 256, PSZ_H,
                        WT + (size_t)tn * 64 * 256, 256, PSZ_WH,
                        bb, P + (size_t)tm * 64 * (Mm + 6), Mm + 6,
                        tn * 64, Mm + 6, Hh, 3,
                        kP + (size_t)tm * 64 * 256, PSZ_K, shb);
            } else {
                int i2 = it - 72, tm = i2 >> 4, tn = i2 & 15;
                tile_pp(pH + (size_t)tm * 64 * 256, 256, PSZ_H,
                        pWeaT + (size_t)tn * 64 * 256, 256, PSZ_WEA,
                        bea, g_ea + (size_t)tm * 64 * (2 * Mm), 2 * Mm,
                        tn * 64, 2 * Mm, Hh, 4, 0, 0, shb);
            }
        }
        gridBarrier();

        // F: simw(64) simr(64) + head scalars(16)
        for (int it = blockIdx.x; it < 144; it += NBLK) {
            if (it < 128) {
                int head = it >= 64, i2 = head ? it - 64 : it;
                int tm = i2 >> 4, tn = i2 & 15;
                const u32* kP = head ? pKr : pKw;
                float* S = head ? g_simr : g_simw;
                tile_pp(kP + (size_t)tm * 64 * 256, 256, PSZ_K,
                        pMem + (size_t)tn * 64 * 256, 256, PSZ_MEM,
                        nullptr, S + (size_t)tm * 64 * Nn, Nn,
                        tn * 64, 1 << 30, Mm, 0, 0, 0, shb);
            } else scalars_item(it - 128);
        }
        gridBarrier();

        // G: warp-level address tails (64 block-items, single round)
        for (int it = blockIdx.x; it < 64; it += NBLK)
            tail_warp(it, (float*)shb);
        gridBarrier();
    }

    for (int it = blockIdx.x; it < 32; it += NBLK) {
        int tm = it >> 3, tn = it & 7;
        tile_pp(pH + (size_t)tm * 64 * 256, 256, PSZ_H,
                pWoT + (size_t)tn * 64 * 256, 256, PSZ_WT,
                bo, out + (size_t)(Tt - 1) * Oo + (size_t)tm * 64 * Tt * Oo,
                (size_t)Tt * Oo, tn * 64, Oo, Hh, 2, 0, 0, shb);
    }
}

// ---------------- host --------------------------------------------------------
extern "C" void kernel_launch(void* const* d_in, const int* in_sizes, int n_in,
                              void* d_out, int out_size)
{
    const float* x    = (const float*)d_in[0];
    const float* mem0 = (const float*)d_in[1];
    const float* wr0  = (const float*)d_in[2];
    const float* ww0  = (const float*)d_in[3];
    const float* h0   = (const float*)d_in[4];
    const float* Wx   = (const float*)d_in[5];
    const float* Wr   = (const float*)d_in[6];
    const float* bh   = (const float*)d_in[7];
    const float* Whr  = (const float*)d_in[8];
    const float* bhr  = (const float*)d_in[9];
    const float* Whw  = (const float*)d_in[10];
    const float* bhw  = (const float*)d_in[11];
    const float* Wea  = (const float*)d_in[12];
    const float* bea  = (const float*)d_in[13];
    const float* Wo   = (const float*)d_in[14];
    const float* bo   = (const float*)d_in[15];
    float* out = (float*)d_out;

    cudaFuncSetAttribute(ntm_persistent,
                         cudaFuncAttributeMaxDynamicSharedMemorySize, 122880);
    ntm_persistent<<<NBLK, NTHR, 122880>>>(x, mem0, wr0, ww0, h0, Wx, Wr, bh,
                                           Whr, bhr, Whw, bhw, Wea, bea, Wo, bo, out);
}